// round 9
// baseline (speedup 1.0000x reference)
#include <cuda_runtime.h>
#include <cuda_fp16.h>
#include <cstdint>
#include <stdint.h>
#include <math.h>

namespace {

typedef unsigned int u32;

constexpr int B_  = 16;
constexpr int N_  = 512;
constexpr int K_  = 48;
constexpr int D_  = 128;
constexpr int KP1 = 49;

constexpr int KVH  = 136;             // half stride per kv row (272 B, 16B-aligned)
constexpr int KVAH = KP1 * KVH;       // halfs per atom kv tile (6664)

// word offsets in dynamic smem (regions strictly phase-ordered; liveness audited)
constexpr int SKV   = 0;       // kv half 2*6664 halfs = 6664 w [E..G] ; alias: partials 2048 w [C, H, I]
constexpr int SA    = 6664;    // gaussian f half tile 128 x 40 halfs = 2560 w [B..E]
constexpr int SSC   = 6664;    // raw scores float [a][64][12] = 1536 w       [F..softmax]
constexpr int SU    = 6664;    // u 2*8*132 = 2112 w                          [G..H]
constexpr int SB    = 9224;    // filtW half 32 x 136 = 2176 w -> ends 11400  [start..E]
constexpr int SPH   = 9224;    // p half [a][8][136] = 1088 w                 [D..F]
constexpr int SATT  = 9224;    // attn float [a][49][12] = 1176 w             [softmax..G]
constexpr int SX    = 11400;   // 256
constexpr int SQ    = 11656;   // 256
constexpr int SAGG  = 11912;   // 256
constexpr int SC_   = 12168;   // 128
constexpr int SLR   = 12296;   // 128
constexpr int SMK   = 12424;   // 128
constexpr int SZJ   = 12552;   // 128 ints
constexpr int SMEM_FLOATS = 12680;
constexpr int SMEM_BYTES  = SMEM_FLOATS * 4;   // 50720

__device__ __forceinline__ void ldsm4(u32* r, u32 a) {
    asm volatile("ldmatrix.sync.aligned.m8n8.x4.shared.b16 {%0,%1,%2,%3}, [%4];"
        : "=r"(r[0]), "=r"(r[1]), "=r"(r[2]), "=r"(r[3]) : "r"(a));
}
__device__ __forceinline__ void ldsm4t(u32* r, u32 a) {
    asm volatile("ldmatrix.sync.aligned.m8n8.x4.trans.shared.b16 {%0,%1,%2,%3}, [%4];"
        : "=r"(r[0]), "=r"(r[1]), "=r"(r[2]), "=r"(r[3]) : "r"(a));
}
__device__ __forceinline__ void mma16816(float* acc, const u32* a,
                                         u32 b0, u32 b1) {
    asm volatile(
        "mma.sync.aligned.m16n8k16.row.col.f32.f16.f16.f32 "
        "{%0,%1,%2,%3}, {%4,%5,%6,%7}, {%8,%9}, {%0,%1,%2,%3};"
        : "+f"(acc[0]), "+f"(acc[1]), "+f"(acc[2]), "+f"(acc[3])
        : "r"(a[0]), "r"(a[1]), "r"(a[2]), "r"(a[3]), "r"(b0), "r"(b1));
}
__device__ __forceinline__ u32 smem_u32(const void* p) {
    return (u32)__cvta_generic_to_shared(const_cast<void*>(p));
}

__global__ void __launch_bounds__(256, 4)
tdt_kernel(const float* __restrict__ positions,
           const int*   __restrict__ z,
           const int*   __restrict__ neighbors,
           const float* __restrict__ nmask,
           const float* __restrict__ embedding,
           const float* __restrict__ filtW,
           const float* __restrict__ filtb,
           const float* __restrict__ Wq,
           const float* __restrict__ Wk,
           const float* __restrict__ Wv,
           const float* __restrict__ Wo,
           float*       __restrict__ out)
{
    extern __shared__ __align__(16) float sm[];
    int*    smi = (int*)sm;
    __half* kvh = (__half*)sm;            // kv tile at word 0

    const int tid  = threadIdx.x;
    const int lane = tid & 31;
    const int warp = tid >> 5;
    const int c    = tid & 127;
    const int er   = tid >> 7;
    const int c4   = tid & 31;
    const int g8   = tid >> 5;
    const int cc   = c4 * 4;

    const int atomBase = blockIdx.x * 2;

    // center embeddings
    sm[SX + er * 128 + c] = embedding[z[atomBase + er] * D_ + c];

    // ---- filtW -> half B tile (stride 136) ----
    {
        __half* bb = (__half*)sm + SB * 2;
        for (int idx = tid; idx < 32 * 128; idx += 256) {
            const int g = idx >> 7, n = idx & 127;
            bb[g * 136 + n] = __float2half(filtW[idx]);
        }
    }

    // ---- Phase A: per-neighbor scalars ----
    if (tid < 128) {
        const int a = tid >> 6;
        const int j = tid & 63;
        if (j < KP1) {
            const int atom = atomBase + a;
            const int b    = atom >> 9;
            float r, mk; int zjv;
            if (j == 0) { r = 0.01f; mk = 1.0f; zjv = z[atom]; }
            else {
                const int nb = neighbors[atom * K_ + j - 1];
                const float dx = positions[(b * N_ + nb) * 3 + 0] - positions[atom * 3 + 0];
                const float dy = positions[(b * N_ + nb) * 3 + 1] - positions[atom * 3 + 1];
                const float dz = positions[(b * N_ + nb) * 3 + 2] - positions[atom * 3 + 2];
                r   = sqrtf(dx * dx + dy * dy + dz * dz + 1e-12f);
                mk  = nmask[atom * K_ + j - 1];
                zjv = z[b * N_ + nb];
            }
            sm[SLR + a * 64 + j] = __logf(r);
            sm[SC_ + a * 64 + j] = (r < 5.0f) ? (0.5f * (__cosf(r * 0.6283185307f) + 1.0f)) : 0.0f;
            sm[SMK + a * 64 + j] = mk;
            smi[SZJ + a * 64 + j] = zjv;
        }
    }
    __syncthreads();

    // ---- Phase B: gaussians -> fp16 A tile (row = a*64+j, stride 40 halfs) ----
    {
        const float OFF0  = -2.3025850930f;
        const float STEP  =  0.1261942905f;
        const float COEFF = -0.5f / (STEP * STEP);
        __half2* ah = (__half2*)sm;       // half2 index == word index
        for (int idx = tid; idx < 2 * KP1 * 16; idx += 256) {
            const int a   = idx / 784;
            const int rem = idx - a * 784;
            const int j   = rem >> 4;
            const int gp  = rem & 15;
            const float lr = sm[SLR + a * 64 + j];
            const float o0 = OFF0 + STEP * (float)(2 * gp);
            const float d0 = lr - o0;
            const float d1 = lr - (o0 + STEP);
            ah[SA + (a * 64 + j) * 20 + gp] =
                __floats2half2_rn(__expf(COEFF * d0 * d0), __expf(COEFF * d1 * d1));
        }
        // zero pad rows 49..63 of each atom
        for (int idx = tid; idx < 2 * 15 * 16; idx += 256) {
            const int a   = idx / 240;
            const int rem = idx - a * 240;
            const int j   = 49 + (rem >> 4);
            const int gp  = rem & 15;
            ah[SA + (a * 64 + j) * 20 + gp] = __floats2half2_rn(0.f, 0.f);
        }
    }
    {   // C-mult: q partials
        float4 a0 = make_float4(0.f,0.f,0.f,0.f), a1 = make_float4(0.f,0.f,0.f,0.f);
        #pragma unroll
        for (int i4 = 0; i4 < 4; i4++) {
            const float4 x0 = *(const float4*)&sm[SX + g8 * 16 + i4 * 4];
            const float4 x1 = *(const float4*)&sm[SX + 128 + g8 * 16 + i4 * 4];
            #pragma unroll
            for (int t = 0; t < 4; t++) {
                const int e = g8 * 16 + i4 * 4 + t;
                const float4 wv = *(const float4*)&Wq[e * 128 + cc];
                const float xs0 = (t==0)?x0.x:(t==1)?x0.y:(t==2)?x0.z:x0.w;
                const float xs1 = (t==0)?x1.x:(t==1)?x1.y:(t==2)?x1.z:x1.w;
                a0.x += xs0*wv.x; a0.y += xs0*wv.y; a0.z += xs0*wv.z; a0.w += xs0*wv.w;
                a1.x += xs1*wv.x; a1.y += xs1*wv.y; a1.z += xs1*wv.z; a1.w += xs1*wv.w;
            }
        }
        *(float4*)&sm[SKV + g8 * 256 + cc]       = a0;
        *(float4*)&sm[SKV + g8 * 256 + 128 + cc] = a1;
    }
    __syncthreads();

    // ---- C-reduce -> q ----
    {
        float s = 0.f;
        #pragma unroll
        for (int e8 = 0; e8 < 8; e8++) s += sm[SKV + e8 * 256 + er * 128 + c];
        sm[SQ + er * 128 + c] = s;
    }
    __syncthreads();

    // ---- Phase E: tensor-core filter GEMM + epilogue -> kv (half) ----
    {
        const int wA   = warp >> 2;           // atom
        const int grp  = lane >> 2;
        const int tg   = lane & 3;
        const int jj0  = (warp & 3) * 16 + grp;
        const int jj1  = jj0 + 8;
        const bool ok0 = jj0 < KP1, ok1 = jj1 < KP1;
        const int   zj0 = ok0 ? smi[SZJ + wA * 64 + jj0] : 0;
        const int   zj1 = ok1 ? smi[SZJ + wA * 64 + jj1] : 0;
        const float Cc0 = ok0 ? sm[SC_ + wA * 64 + jj0] : 0.f;
        const float Cc1 = ok1 ? sm[SC_ + wA * 64 + jj1] : 0.f;
        const float* em0 = embedding + zj0 * D_;
        const float* em1 = embedding + zj1 * D_;
        __half* kvb = kvh + wA * KVAH;

        u32 afr[2][4];
        {
            const __half* ab = (const __half*)sm + SA * 2;
            const int lrow = warp * 16 + ((lane & 8) ? 8 : 0) + (lane & 7);
            const int lcol = (lane & 16) ? 8 : 0;
            ldsm4(afr[0], smem_u32(ab + lrow * 40 + lcol));
            ldsm4(afr[1], smem_u32(ab + lrow * 40 + 16 + lcol));
        }
        const __half* bb = (const __half*)sm + SB * 2;
        const int brow = ((lane & 8) ? 8 : 0) + (lane & 7);
        const int bcol = (lane & 16) ? 8 : 0;

        #pragma unroll
        for (int np = 0; np < 8; np++) {
            float acc[8] = {0.f,0.f,0.f,0.f,0.f,0.f,0.f,0.f};
            #pragma unroll
            for (int kk = 0; kk < 2; kk++) {
                u32 bfr[4];
                ldsm4t(bfr, smem_u32(bb + (kk * 16 + brow) * 136 + np * 16 + bcol));
                mma16816(acc + 0, afr[kk], bfr[0], bfr[1]);
                mma16816(acc + 4, afr[kk], bfr[2], bfr[3]);
            }
            #pragma unroll
            for (int t = 0; t < 2; t++) {
                const int c0 = np * 16 + t * 8 + tg * 2;
                const float2 fb2 = *(const float2*)&filtb[c0];
                if (ok0) {
                    const float2 e2 = *(const float2*)&em0[c0];
                    const float v0 = (acc[t*4+0] + fb2.x) * Cc0 * e2.x;
                    const float v1 = (acc[t*4+1] + fb2.y) * Cc0 * e2.y;
                    *(__half2*)&kvb[jj0 * KVH + c0] = __floats2half2_rn(v0, v1);
                }
                if (ok1) {
                    const float2 e2 = *(const float2*)&em1[c0];
                    const float v0 = (acc[t*4+2] + fb2.x) * Cc1 * e2.x;
                    const float v1 = (acc[t*4+3] + fb2.y) * Cc1 * e2.y;
                    *(__half2*)&kvb[jj1 * KVH + c0] = __floats2half2_rn(v0, v1);
                }
            }
        }
    }
    __syncthreads();

    // ---- Phase D: p_a[h][d] = sum_e Wk[d][e] q_a[e] -> fp16 tile [a][h][136] ----
    {
        __half* ph = (__half*)sm + SPH * 2;
        const float4 q0 = *(const float4*)&sm[SQ + lane * 4];
        const float4 q1 = *(const float4*)&sm[SQ + 128 + lane * 4];
        #pragma unroll
        for (int rr = 0; rr < 16; rr++) {
            const int d = warp * 16 + rr;
            const float4 wr = *(const float4*)&Wk[d * D_ + lane * 4];
            float p0 = wr.x * q0.x + wr.y * q0.y + wr.z * q0.z + wr.w * q0.w;
            float p1 = wr.x * q1.x + wr.y * q1.y + wr.z * q1.z + wr.w * q1.w;
            p0 += __shfl_xor_sync(0xffffffffu, p0, 1);
            p0 += __shfl_xor_sync(0xffffffffu, p0, 2);
            p1 += __shfl_xor_sync(0xffffffffu, p1, 1);
            p1 += __shfl_xor_sync(0xffffffffu, p1, 2);
            if ((lane & 3) == 0) {
                const int h = lane >> 2;
                ph[h * 136 + d]        = __float2half(p0);
                ph[1088 + h * 136 + d] = __float2half(p1);
            }
        }
    }
    __syncthreads();

    // ---- Phase F: scores via tensor cores. warp=(atom, m-tile of 16 j) ----
    {
        const int a  = warp >> 2;
        const int mt = warp & 3;
        const __half* kvb = kvh + a * KVAH;
        const __half* pb  = (const __half*)sm + SPH * 2 + a * 1088;
        const int arow = mt * 16 + (lane & 15);
        const int acol = (lane & 16) ? 8 : 0;
        const int brow = lane & 7;
        const int bt   = lane >> 3;
        float acc[4] = {0.f, 0.f, 0.f, 0.f};
        #pragma unroll
        for (int kp = 0; kp < 4; kp++) {
            u32 af0[4], af1[4], bf[4];
            ldsm4(af0, smem_u32(kvb + arow * KVH + kp * 32 + acol));
            ldsm4(af1, smem_u32(kvb + arow * KVH + kp * 32 + 16 + acol));
            ldsm4(bf,  smem_u32(pb + brow * 136 + kp * 32 + bt * 8));
            mma16816(acc, af0, bf[0], bf[1]);
            mma16816(acc, af1, bf[2], bf[3]);
        }
        const int grp = lane >> 2, tg = lane & 3;
        float* ss = &sm[SSC + a * 768];
        const int j0 = mt * 16 + grp;
        *(float2*)&ss[j0 * 12 + tg * 2]       = make_float2(acc[0], acc[1]);
        *(float2*)&ss[(j0 + 8) * 12 + tg * 2] = make_float2(acc[2], acc[3]);
    }
    __syncthreads();

    // ---- softmax: warp = head; reads scores [j][12], writes attn [j][12] at SATT ----
    {
        const int h = warp;
        #pragma unroll
        for (int a = 0; a < 2; a++) {
            const float* ss = &sm[SSC + a * 768];
            float v0 = ss[lane * 12 + h];
            float v1 = (lane + 32 < KP1) ? ss[(lane + 32) * 12 + h] : 0.f;
            v0 = (sm[SMK + a * 64 + lane] > 0.f) ? v0 * 0.25f : -1e9f;
            const int j1 = lane + 32;
            if (j1 < KP1) v1 = (sm[SMK + a * 64 + j1] > 0.f) ? v1 * 0.25f : -1e9f;
            else          v1 = -3.0e38f;
            float m = fmaxf(v0, v1);
            #pragma unroll
            for (int o = 16; o > 0; o >>= 1)
                m = fmaxf(m, __shfl_xor_sync(0xffffffffu, m, o));
            const float e0 = __expf(v0 - m);
            const float e1 = (j1 < KP1) ? __expf(v1 - m) : 0.f;
            float ssum = e0 + e1;
            #pragma unroll
            for (int o = 16; o > 0; o >>= 1)
                ssum += __shfl_xor_sync(0xffffffffu, ssum, o);
            const float inv = 1.0f / ssum;
            sm[SATT + a * 588 + lane * 12 + h] = e0 * inv;
            if (j1 < KP1) sm[SATT + a * 588 + j1 * 12 + h] = e1 * inv;
        }
    }
    __syncthreads();

    // ---- Phase G: u[a][h][c] = sum_j attn[j][h] * kv[j][c] ----
    {
        const int a = er;
        const __half* kvc = &kvh[a * KVAH + c];
        const float*  atb = &sm[SATT + a * 588];
        float acc[8];
        #pragma unroll
        for (int h = 0; h < 8; h++) acc[h] = 0.f;
        #pragma unroll 7
        for (int j = 0; j < KP1; j++) {
            const float4 t0 = *(const float4*)&atb[j * 12];
            const float4 t1 = *(const float4*)&atb[j * 12 + 4];
            const float kvd = __half2float(kvc[j * KVH]);
            acc[0] += t0.x * kvd; acc[1] += t0.y * kvd;
            acc[2] += t0.z * kvd; acc[3] += t0.w * kvd;
            acc[4] += t1.x * kvd; acc[5] += t1.y * kvd;
            acc[6] += t1.z * kvd; acc[7] += t1.w * kvd;
        }
        #pragma unroll
        for (int h = 0; h < 8; h++) sm[SU + a * 1056 + h * 132 + c] = acc[h];
    }
    __syncthreads();

    // ---- Phase H-mult: agg partials ----
    {
        const int h = cc >> 4;
        float4 a0 = make_float4(0.f,0.f,0.f,0.f), a1 = make_float4(0.f,0.f,0.f,0.f);
        #pragma unroll
        for (int i4 = 0; i4 < 4; i4++) {
            const float4 u0 = *(const float4*)&sm[SU + h * 132 + g8 * 16 + i4 * 4];
            const float4 u1 = *(const float4*)&sm[SU + 1056 + h * 132 + g8 * 16 + i4 * 4];
            #pragma unroll
            for (int t = 0; t < 4; t++) {
                const int d = g8 * 16 + i4 * 4 + t;
                const float4 wv = *(const float4*)&Wv[d * 128 + cc];
                const float us0 = (t==0)?u0.x:(t==1)?u0.y:(t==2)?u0.z:u0.w;
                const float us1 = (t==0)?u1.x:(t==1)?u1.y:(t==2)?u1.z:u1.w;
                a0.x += us0*wv.x; a0.y += us0*wv.y; a0.z += us0*wv.z; a0.w += us0*wv.w;
                a1.x += us1*wv.x; a1.y += us1*wv.y; a1.z += us1*wv.z; a1.w += us1*wv.w;
            }
        }
        *(float4*)&sm[SKV + g8 * 256 + cc]       = a0;   // kv dead (G done)
        *(float4*)&sm[SKV + g8 * 256 + 128 + cc] = a1;
    }
    __syncthreads();

    // ---- H-reduce -> agg ----
    {
        float s = 0.f;
        #pragma unroll
        for (int d8 = 0; d8 < 8; d8++) s += sm[SKV + d8 * 256 + er * 128 + c];
        sm[SAGG + er * 128 + c] = s;
    }
    __syncthreads();

    // ---- Phase I-mult: out partials ----
    {
        float4 a0 = make_float4(0.f,0.f,0.f,0.f), a1 = make_float4(0.f,0.f,0.f,0.f);
        #pragma unroll
        for (int i4 = 0; i4 < 4; i4++) {
            const float4 x0 = *(const float4*)&sm[SAGG + g8 * 16 + i4 * 4];
            const float4 x1 = *(const float4*)&sm[SAGG + 128 + g8 * 16 + i4 * 4];
            #pragma unroll
            for (int t = 0; t < 4; t++) {
                const int e = g8 * 16 + i4 * 4 + t;
                const float4 wv = *(const float4*)&Wo[e * 128 + cc];
                const float xs0 = (t==0)?x0.x:(t==1)?x0.y:(t==2)?x0.z:x0.w;
                const float xs1 = (t==0)?x1.x:(t==1)?x1.y:(t==2)?x1.z:x1.w;
                a0.x += xs0*wv.x; a0.y += xs0*wv.y; a0.z += xs0*wv.z; a0.w += xs0*wv.w;
                a1.x += xs1*wv.x; a1.y += xs1*wv.y; a1.z += xs1*wv.z; a1.w += xs1*wv.w;
            }
        }
        __syncthreads();
        *(float4*)&sm[SKV + g8 * 256 + cc]       = a0;
        *(float4*)&sm[SKV + g8 * 256 + 128 + cc] = a1;
    }
    __syncthreads();

    // ---- I-reduce + residual -> out ----
    {
        float s = 0.f;
        #pragma unroll
        for (int e8 = 0; e8 < 8; e8++) s += sm[SKV + e8 * 256 + er * 128 + c];
        out[(atomBase + er) * D_ + c] = sm[SX + er * 128 + c] + s;
    }
}

} // namespace

extern "C" void kernel_launch(void* const* d_in, const int* in_sizes, int n_in,
                              void* d_out, int out_size) {
    (void)in_sizes; (void)n_in; (void)out_size;
    cudaFuncSetAttribute(tdt_kernel,
                         cudaFuncAttributeMaxDynamicSharedMemorySize, SMEM_BYTES);
    tdt_kernel<<<B_ * N_ / 2, 256, SMEM_BYTES>>>(
        (const float*)d_in[0],   // positions
        (const int*)  d_in[1],   // z
        (const int*)  d_in[2],   // neighbors
        (const float*)d_in[3],   // neighbor_mask
        (const float*)d_in[4],   // embedding
        (const float*)d_in[5],   // filt_W
        (const float*)d_in[6],   // filt_b
        (const float*)d_in[7],   // Wq
        (const float*)d_in[8],   // Wk
        (const float*)d_in[9],   // Wv
        (const float*)d_in[10],  // Wo
        (float*)d_out);
}

// round 10
// speedup vs baseline: 1.3289x; 1.3289x over previous
#include <cuda_runtime.h>
#include <cuda_fp16.h>
#include <cstdint>
#include <stdint.h>
#include <math.h>

namespace {

typedef unsigned int u32;

constexpr int B_  = 16;
constexpr int N_  = 512;
constexpr int K_  = 48;
constexpr int D_  = 128;
constexpr int KP1 = 49;

constexpr int KVH  = 136;             // half stride per kv row (272 B, 16B-aligned)
constexpr int KVAH = KP1 * KVH;       // halfs per atom kv tile (6664)

// word offsets in dynamic smem (liveness audited per phase)
constexpr int SKV   = 0;       // kv half 2*6664 halfs = 6664 w [E..G] ; alias: partials 2048 w [C,H,I]
constexpr int SA    = 6664;    // gaussian f half tile 128 x 40 halfs = 2560 w [B..E]
constexpr int SSC   = 6664;    // score partials 2048 w -> 6664..8712            [F..softmax]
constexpr int SU    = 6664;    // u 2*8*132 = 2112 w -> 6664..8776               [G..H]
constexpr int SATT  = 8776;    // attn float [a][49][12] = 1176 w -> 8776..9952  [softmax..G]
constexpr int SB    = 9224;    // filtW half 32 x 136 = 2176 w -> ends 11400     [start..E]
constexpr int SPH   = 9224;    // p half [a][8][136] = 1088 w (aliases dead SB)  [D..F]
constexpr int SX    = 11400;   // 256
constexpr int SQ    = 11656;   // 256
constexpr int SAGG  = 11912;   // 256
constexpr int SC_   = 12168;   // 128
constexpr int SLR   = 12296;   // 128
constexpr int SMK   = 12424;   // 128
constexpr int SZJ   = 12552;   // 128 ints
constexpr int SMEM_FLOATS = 12680;
constexpr int SMEM_BYTES  = SMEM_FLOATS * 4;   // 50720

__device__ __forceinline__ void ldsm4(u32* r, u32 a) {
    asm volatile("ldmatrix.sync.aligned.m8n8.x4.shared.b16 {%0,%1,%2,%3}, [%4];"
        : "=r"(r[0]), "=r"(r[1]), "=r"(r[2]), "=r"(r[3]) : "r"(a));
}
__device__ __forceinline__ void ldsm4t(u32* r, u32 a) {
    asm volatile("ldmatrix.sync.aligned.m8n8.x4.trans.shared.b16 {%0,%1,%2,%3}, [%4];"
        : "=r"(r[0]), "=r"(r[1]), "=r"(r[2]), "=r"(r[3]) : "r"(a));
}
__device__ __forceinline__ void mma16816(float* acc, const u32* a,
                                         u32 b0, u32 b1) {
    asm volatile(
        "mma.sync.aligned.m16n8k16.row.col.f32.f16.f16.f32 "
        "{%0,%1,%2,%3}, {%4,%5,%6,%7}, {%8,%9}, {%0,%1,%2,%3};"
        : "+f"(acc[0]), "+f"(acc[1]), "+f"(acc[2]), "+f"(acc[3])
        : "r"(a[0]), "r"(a[1]), "r"(a[2]), "r"(a[3]), "r"(b0), "r"(b1));
}
__device__ __forceinline__ u32 smem_u32(const void* p) {
    return (u32)__cvta_generic_to_shared(const_cast<void*>(p));
}

__global__ void __launch_bounds__(256, 4)
tdt_kernel(const float* __restrict__ positions,
           const int*   __restrict__ z,
           const int*   __restrict__ neighbors,
           const float* __restrict__ nmask,
           const float* __restrict__ embedding,
           const float* __restrict__ filtW,
           const float* __restrict__ filtb,
           const float* __restrict__ Wq,
           const float* __restrict__ Wk,
           const float* __restrict__ Wv,
           const float* __restrict__ Wo,
           float*       __restrict__ out)
{
    extern __shared__ __align__(16) float sm[];
    int*    smi = (int*)sm;
    __half* kvh = (__half*)sm;            // kv tile at word 0

    const int tid  = threadIdx.x;
    const int lane = tid & 31;
    const int warp = tid >> 5;
    const int c    = tid & 127;
    const int er   = tid >> 7;
    const int c4   = tid & 31;
    const int g8   = tid >> 5;
    const int cc   = c4 * 4;

    const int atomBase = blockIdx.x * 2;

    // center embeddings
    sm[SX + er * 128 + c] = embedding[z[atomBase + er] * D_ + c];

    // ---- filtW -> half B tile (stride 136) ----
    {
        __half* bb = (__half*)sm + SB * 2;
        for (int idx = tid; idx < 32 * 128; idx += 256) {
            const int g = idx >> 7, n = idx & 127;
            bb[g * 136 + n] = __float2half(filtW[idx]);
        }
    }

    // ---- Phase A: per-neighbor scalars ----
    if (tid < 128) {
        const int a = tid >> 6;
        const int j = tid & 63;
        if (j < KP1) {
            const int atom = atomBase + a;
            const int b    = atom >> 9;
            float r, mk; int zjv;
            if (j == 0) { r = 0.01f; mk = 1.0f; zjv = z[atom]; }
            else {
                const int nb = neighbors[atom * K_ + j - 1];
                const float dx = positions[(b * N_ + nb) * 3 + 0] - positions[atom * 3 + 0];
                const float dy = positions[(b * N_ + nb) * 3 + 1] - positions[atom * 3 + 1];
                const float dz = positions[(b * N_ + nb) * 3 + 2] - positions[atom * 3 + 2];
                r   = sqrtf(dx * dx + dy * dy + dz * dz + 1e-12f);
                mk  = nmask[atom * K_ + j - 1];
                zjv = z[b * N_ + nb];
            }
            sm[SLR + a * 64 + j] = __logf(r);
            sm[SC_ + a * 64 + j] = (r < 5.0f) ? (0.5f * (__cosf(r * 0.6283185307f) + 1.0f)) : 0.0f;
            sm[SMK + a * 64 + j] = mk;
            smi[SZJ + a * 64 + j] = zjv;
        }
    }
    __syncthreads();

    // ---- Phase B: gaussians -> fp16 A tile (row = a*64+j, stride 40 halfs) ----
    {
        const float OFF0  = -2.3025850930f;
        const float STEP  =  0.1261942905f;
        const float COEFF = -0.5f / (STEP * STEP);
        __half2* ah = (__half2*)sm;       // half2 index == word index
        for (int idx = tid; idx < 2 * KP1 * 16; idx += 256) {
            const int a   = idx / 784;
            const int rem = idx - a * 784;
            const int j   = rem >> 4;
            const int gp  = rem & 15;
            const float lr = sm[SLR + a * 64 + j];
            const float o0 = OFF0 + STEP * (float)(2 * gp);
            const float d0 = lr - o0;
            const float d1 = lr - (o0 + STEP);
            ah[SA + (a * 64 + j) * 20 + gp] =
                __floats2half2_rn(__expf(COEFF * d0 * d0), __expf(COEFF * d1 * d1));
        }
        // zero pad rows 49..63 of each atom
        for (int idx = tid; idx < 2 * 15 * 16; idx += 256) {
            const int a   = idx / 240;
            const int rem = idx - a * 240;
            const int j   = 49 + (rem >> 4);
            const int gp  = rem & 15;
            ah[SA + (a * 64 + j) * 20 + gp] = __floats2half2_rn(0.f, 0.f);
        }
    }
    {   // C-mult: q partials
        float4 a0 = make_float4(0.f,0.f,0.f,0.f), a1 = make_float4(0.f,0.f,0.f,0.f);
        #pragma unroll
        for (int i4 = 0; i4 < 4; i4++) {
            const float4 x0 = *(const float4*)&sm[SX + g8 * 16 + i4 * 4];
            const float4 x1 = *(const float4*)&sm[SX + 128 + g8 * 16 + i4 * 4];
            #pragma unroll
            for (int t = 0; t < 4; t++) {
                const int e = g8 * 16 + i4 * 4 + t;
                const float4 wv = *(const float4*)&Wq[e * 128 + cc];
                const float xs0 = (t==0)?x0.x:(t==1)?x0.y:(t==2)?x0.z:x0.w;
                const float xs1 = (t==0)?x1.x:(t==1)?x1.y:(t==2)?x1.z:x1.w;
                a0.x += xs0*wv.x; a0.y += xs0*wv.y; a0.z += xs0*wv.z; a0.w += xs0*wv.w;
                a1.x += xs1*wv.x; a1.y += xs1*wv.y; a1.z += xs1*wv.z; a1.w += xs1*wv.w;
            }
        }
        *(float4*)&sm[SKV + g8 * 256 + cc]       = a0;
        *(float4*)&sm[SKV + g8 * 256 + 128 + cc] = a1;
    }
    __syncthreads();

    // ---- C-reduce -> q ----
    {
        float s = 0.f;
        #pragma unroll
        for (int e8 = 0; e8 < 8; e8++) s += sm[SKV + e8 * 256 + er * 128 + c];
        sm[SQ + er * 128 + c] = s;
    }
    __syncthreads();

    // ---- Phase E: tensor-core filter GEMM + epilogue -> kv (half) ----
    {
        const int wA   = warp >> 2;           // atom
        const int grp  = lane >> 2;
        const int tg   = lane & 3;
        const int jj0  = (warp & 3) * 16 + grp;
        const int jj1  = jj0 + 8;
        const bool ok0 = jj0 < KP1, ok1 = jj1 < KP1;
        const int   zj0 = ok0 ? smi[SZJ + wA * 64 + jj0] : 0;
        const int   zj1 = ok1 ? smi[SZJ + wA * 64 + jj1] : 0;
        const float Cc0 = ok0 ? sm[SC_ + wA * 64 + jj0] : 0.f;
        const float Cc1 = ok1 ? sm[SC_ + wA * 64 + jj1] : 0.f;
        const float* em0 = embedding + zj0 * D_;
        const float* em1 = embedding + zj1 * D_;
        __half* kvb = kvh + wA * KVAH;

        u32 afr[2][4];
        {
            const __half* ab = (const __half*)sm + SA * 2;
            const int lrow = warp * 16 + ((lane & 8) ? 8 : 0) + (lane & 7);
            const int lcol = (lane & 16) ? 8 : 0;
            ldsm4(afr[0], smem_u32(ab + lrow * 40 + lcol));
            ldsm4(afr[1], smem_u32(ab + lrow * 40 + 16 + lcol));
        }
        const __half* bb = (const __half*)sm + SB * 2;
        const int brow = ((lane & 8) ? 8 : 0) + (lane & 7);
        const int bcol = (lane & 16) ? 8 : 0;

        #pragma unroll
        for (int np = 0; np < 8; np++) {
            float acc[8] = {0.f,0.f,0.f,0.f,0.f,0.f,0.f,0.f};
            #pragma unroll
            for (int kk = 0; kk < 2; kk++) {
                u32 bfr[4];
                ldsm4t(bfr, smem_u32(bb + (kk * 16 + brow) * 136 + np * 16 + bcol));
                mma16816(acc + 0, afr[kk], bfr[0], bfr[1]);
                mma16816(acc + 4, afr[kk], bfr[2], bfr[3]);
            }
            #pragma unroll
            for (int t = 0; t < 2; t++) {
                const int c0 = np * 16 + t * 8 + tg * 2;
                const float2 fb2 = *(const float2*)&filtb[c0];
                if (ok0) {
                    const float2 e2 = *(const float2*)&em0[c0];
                    const float v0 = (acc[t*4+0] + fb2.x) * Cc0 * e2.x;
                    const float v1 = (acc[t*4+1] + fb2.y) * Cc0 * e2.y;
                    *(__half2*)&kvb[jj0 * KVH + c0] = __floats2half2_rn(v0, v1);
                }
                if (ok1) {
                    const float2 e2 = *(const float2*)&em1[c0];
                    const float v0 = (acc[t*4+2] + fb2.x) * Cc1 * e2.x;
                    const float v1 = (acc[t*4+3] + fb2.y) * Cc1 * e2.y;
                    *(__half2*)&kvb[jj1 * KVH + c0] = __floats2half2_rn(v0, v1);
                }
            }
        }
    }
    __syncthreads();

    // ---- Phase D: p_a[h][d] = sum_e Wk[d][e] q_a[e] -> fp16 tile [a][8][136] ----
    {
        __half* ph = (__half*)sm + SPH * 2;
        const float4 q0 = *(const float4*)&sm[SQ + lane * 4];
        const float4 q1 = *(const float4*)&sm[SQ + 128 + lane * 4];
        #pragma unroll
        for (int rr = 0; rr < 16; rr++) {
            const int d = warp * 16 + rr;
            const float4 wr = *(const float4*)&Wk[d * D_ + lane * 4];
            float p0 = wr.x * q0.x + wr.y * q0.y + wr.z * q0.z + wr.w * q0.w;
            float p1 = wr.x * q1.x + wr.y * q1.y + wr.z * q1.z + wr.w * q1.w;
            p0 += __shfl_xor_sync(0xffffffffu, p0, 1);
            p0 += __shfl_xor_sync(0xffffffffu, p0, 2);
            p1 += __shfl_xor_sync(0xffffffffu, p1, 1);
            p1 += __shfl_xor_sync(0xffffffffu, p1, 2);
            if ((lane & 3) == 0) {
                const int h = lane >> 2;
                ph[h * 136 + d]        = __float2half(p0);
                ph[1088 + h * 136 + d] = __float2half(p1);
            }
        }
    }
    __syncthreads();

    // ---- Phase F (R8 structure): partial scores; p now fp16 (1 uint4 per (h,c8)) ----
    {
        const int task  = warp >> 1;
        const int a     = task >> 1;
        const int rep   = task & 1;
        const int dhalf = warp & 1;
        const int j     = rep * 32 + lane;
        float acc[8];
        #pragma unroll
        for (int h = 0; h < 8; h++) acc[h] = 0.f;
        if (j < KP1) {
            const uint4* kvr = (const uint4*)&kvh[a * KVAH + j * KVH + dhalf * 64];
            const __half* pb = (const __half*)sm + SPH * 2 + a * 1088 + dhalf * 64;
            #pragma unroll
            for (int c8 = 0; c8 < 8; c8++) {
                const uint4 raw = kvr[c8];
                const float2 f01 = __half22float2(*(const __half2*)&raw.x);
                const float2 f23 = __half22float2(*(const __half2*)&raw.y);
                const float2 f45 = __half22float2(*(const __half2*)&raw.z);
                const float2 f67 = __half22float2(*(const __half2*)&raw.w);
                #pragma unroll
                for (int h = 0; h < 8; h++) {
                    const uint4 praw = *(const uint4*)&pb[h * 136 + c8 * 8];
                    const float2 p01 = __half22float2(*(const __half2*)&praw.x);
                    const float2 p23 = __half22float2(*(const __half2*)&praw.y);
                    const float2 p45 = __half22float2(*(const __half2*)&praw.z);
                    const float2 p67 = __half22float2(*(const __half2*)&praw.w);
                    acc[h] += f01.x*p01.x + f01.y*p01.y + f23.x*p23.x + f23.y*p23.y
                            + f45.x*p45.x + f45.y*p45.y + f67.x*p67.x + f67.y*p67.y;
                }
            }
        }
        #pragma unroll
        for (int h = 0; h < 8; h++)
            sm[SSC + ((task * 2 + dhalf) * 8 + h) * 32 + lane] = acc[h];
    }
    __syncthreads();

    // ---- softmax: warp = head; combines dhalf partials; writes attn [j][12] ----
    {
        const int h = warp;
        #pragma unroll
        for (int a = 0; a < 2; a++) {
            const int t0 = a * 2, t1 = a * 2 + 1;
            float v0 = sm[SSC + ((t0*2+0)*8 + h)*32 + lane]
                     + sm[SSC + ((t0*2+1)*8 + h)*32 + lane];
            float v1 = (lane < 17) ? sm[SSC + ((t1*2+0)*8 + h)*32 + lane]
                                   + sm[SSC + ((t1*2+1)*8 + h)*32 + lane] : 0.f;
            v0 = (sm[SMK + a * 64 + lane] > 0.f) ? v0 * 0.25f : -1e9f;
            const int j1 = lane + 32;
            if (j1 < KP1) v1 = (sm[SMK + a * 64 + j1] > 0.f) ? v1 * 0.25f : -1e9f;
            else          v1 = -3.0e38f;
            float m = fmaxf(v0, v1);
            #pragma unroll
            for (int o = 16; o > 0; o >>= 1)
                m = fmaxf(m, __shfl_xor_sync(0xffffffffu, m, o));
            const float e0 = __expf(v0 - m);
            const float e1 = (j1 < KP1) ? __expf(v1 - m) : 0.f;
            float ssum = e0 + e1;
            #pragma unroll
            for (int o = 16; o > 0; o >>= 1)
                ssum += __shfl_xor_sync(0xffffffffu, ssum, o);
            const float inv = 1.0f / ssum;
            sm[SATT + a * 588 + lane * 12 + h] = e0 * inv;
            if (j1 < KP1) sm[SATT + a * 588 + j1 * 12 + h] = e1 * inv;
        }
    }
    __syncthreads();

    // ---- Phase G: u[a][h][c] = sum_j attn[j][h] * kv[j][c] ----
    {
        const int a = er;
        const __half* kvc = &kvh[a * KVAH + c];
        const float*  atb = &sm[SATT + a * 588];
        float acc[8];
        #pragma unroll
        for (int h = 0; h < 8; h++) acc[h] = 0.f;
        #pragma unroll 7
        for (int j = 0; j < KP1; j++) {
            const float4 t0 = *(const float4*)&atb[j * 12];
            const float4 t1 = *(const float4*)&atb[j * 12 + 4];
            const float kvd = __half2float(kvc[j * KVH]);
            acc[0] += t0.x * kvd; acc[1] += t0.y * kvd;
            acc[2] += t0.z * kvd; acc[3] += t0.w * kvd;
            acc[4] += t1.x * kvd; acc[5] += t1.y * kvd;
            acc[6] += t1.z * kvd; acc[7] += t1.w * kvd;
        }
        #pragma unroll
        for (int h = 0; h < 8; h++) sm[SU + a * 1056 + h * 132 + c] = acc[h];
    }
    __syncthreads();

    // ---- Phase H-mult: agg partials ----
    {
        const int h = cc >> 4;
        float4 a0 = make_float4(0.f,0.f,0.f,0.f), a1 = make_float4(0.f,0.f,0.f,0.f);
        #pragma unroll
        for (int i4 = 0; i4 < 4; i4++) {
            const float4 u0 = *(const float4*)&sm[SU + h * 132 + g8 * 16 + i4 * 4];
            const float4 u1 = *(const float4*)&sm[SU + 1056 + h * 132 + g8 * 16 + i4 * 4];
            #pragma unroll
            for (int t = 0; t < 4; t++) {
                const int d = g8 * 16 + i4 * 4 + t;
                const float4 wv = *(const float4*)&Wv[d * 128 + cc];
                const float us0 = (t==0)?u0.x:(t==1)?u0.y:(t==2)?u0.z:u0.w;
                const float us1 = (t==0)?u1.x:(t==1)?u1.y:(t==2)?u1.z:u1.w;
                a0.x += us0*wv.x; a0.y += us0*wv.y; a0.z += us0*wv.z; a0.w += us0*wv.w;
                a1.x += us1*wv.x; a1.y += us1*wv.y; a1.z += us1*wv.z; a1.w += us1*wv.w;
            }
        }
        __syncthreads();   // u reads complete before partials overwrite SKV region
        *(float4*)&sm[SKV + g8 * 256 + cc]       = a0;
        *(float4*)&sm[SKV + g8 * 256 + 128 + cc] = a1;
    }
    __syncthreads();

    // ---- H-reduce -> agg ----
    {
        float s = 0.f;
        #pragma unroll
        for (int d8 = 0; d8 < 8; d8++) s += sm[SKV + d8 * 256 + er * 128 + c];
        sm[SAGG + er * 128 + c] = s;
    }
    __syncthreads();

    // ---- Phase I-mult: out partials ----
    {
        float4 a0 = make_float4(0.f,0.f,0.f,0.f), a1 = make_float4(0.f,0.f,0.f,0.f);
        #pragma unroll
        for (int i4 = 0; i4 < 4; i4++) {
            const float4 x0 = *(const float4*)&sm[SAGG + g8 * 16 + i4 * 4];
            const float4 x1 = *(const float4*)&sm[SAGG + 128 + g8 * 16 + i4 * 4];
            #pragma unroll
            for (int t = 0; t < 4; t++) {
                const int e = g8 * 16 + i4 * 4 + t;
                const float4 wv = *(const float4*)&Wo[e * 128 + cc];
                const float xs0 = (t==0)?x0.x:(t==1)?x0.y:(t==2)?x0.z:x0.w;
                const float xs1 = (t==0)?x1.x:(t==1)?x1.y:(t==2)?x1.z:x1.w;
                a0.x += xs0*wv.x; a0.y += xs0*wv.y; a0.z += xs0*wv.z; a0.w += xs0*wv.w;
                a1.x += xs1*wv.x; a1.y += xs1*wv.y; a1.z += xs1*wv.z; a1.w += xs1*wv.w;
            }
        }
        __syncthreads();
        *(float4*)&sm[SKV + g8 * 256 + cc]       = a0;
        *(float4*)&sm[SKV + g8 * 256 + 128 + cc] = a1;
    }
    __syncthreads();

    // ---- I-reduce + residual -> out ----
    {
        float s = 0.f;
        #pragma unroll
        for (int e8 = 0; e8 < 8; e8++) s += sm[SKV + e8 * 256 + er * 128 + c];
        out[(atomBase + er) * D_ + c] = sm[SX + er * 128 + c] + s;
    }
}

} // namespace

extern "C" void kernel_launch(void* const* d_in, const int* in_sizes, int n_in,
                              void* d_out, int out_size) {
    (void)in_sizes; (void)n_in; (void)out_size;
    cudaFuncSetAttribute(tdt_kernel,
                         cudaFuncAttributeMaxDynamicSharedMemorySize, SMEM_BYTES);
    tdt_kernel<<<B_ * N_ / 2, 256, SMEM_BYTES>>>(
        (const float*)d_in[0],   // positions
        (const int*)  d_in[1],   // z
        (const int*)  d_in[2],   // neighbors
        (const float*)d_in[3],   // neighbor_mask
        (const float*)d_in[4],   // embedding
        (const float*)d_in[5],   // filt_W
        (const float*)d_in[6],   // filt_b
        (const float*)d_in[7],   // Wq
        (const float*)d_in[8],   // Wk
        (const float*)d_in[9],   // Wv
        (const float*)d_in[10],  // Wo
        (float*)d_out);
}

// round 11
// speedup vs baseline: 1.3881x; 1.0445x over previous
#include <cuda_runtime.h>
#include <cuda_fp16.h>
#include <cstdint>
#include <stdint.h>
#include <math.h>

namespace {

typedef unsigned int u32;

constexpr int B_  = 16;
constexpr int N_  = 512;
constexpr int K_  = 48;
constexpr int D_  = 128;
constexpr int KP1 = 49;
constexpr int ATOMS = 4;
constexpr int THREADS = 512;

constexpr int KVH  = 136;             // half stride per kv row
constexpr int KVAH = KP1 * KVH;       // 6664 halfs per atom kv tile

// word offsets (liveness audited)
constexpr int SKV   = 0;       // kv half 4*6664 = 13328 w [E..G] ; alias: C/H/I partials 8192 w
constexpr int SA    = 13328;   // gaussian f half tile 256 x 40 halfs = 5120 w [B..E]
constexpr int SSC   = 13328;   // score partials 4096 w (alias, SA dead)      [F..softmax]
constexpr int SU    = 13328;   // u 4*8*132 = 4224 w (alias, SSC dead)        [G..H]
constexpr int SATT  = 18448;   // attn half [a][64][8] = 2048 halfs = 1024 w  [softmax..G]
constexpr int SB    = 19472;   // filtW half 32*136 = 2176 w                  [start..E]
constexpr int SPH   = 19472;   // p half [a][8][136] = 2176 w (alias dead SB) [D..F]
constexpr int SX    = 21648;   // 512
constexpr int SQ    = 22160;   // 512
constexpr int SAGG  = 22672;   // 512
constexpr int SC_   = 23184;   // 256
constexpr int SLR   = 23440;   // 256
constexpr int SMK   = 23696;   // 256
constexpr int SZJ   = 23952;   // 256 ints
constexpr int SMEM_FLOATS = 24208;
constexpr int SMEM_BYTES  = SMEM_FLOATS * 4;   // 96832 -> 2 CTAs/SM

__device__ __forceinline__ void ldsm4(u32* r, u32 a) {
    asm volatile("ldmatrix.sync.aligned.m8n8.x4.shared.b16 {%0,%1,%2,%3}, [%4];"
        : "=r"(r[0]), "=r"(r[1]), "=r"(r[2]), "=r"(r[3]) : "r"(a));
}
__device__ __forceinline__ void ldsm4t(u32* r, u32 a) {
    asm volatile("ldmatrix.sync.aligned.m8n8.x4.trans.shared.b16 {%0,%1,%2,%3}, [%4];"
        : "=r"(r[0]), "=r"(r[1]), "=r"(r[2]), "=r"(r[3]) : "r"(a));
}
__device__ __forceinline__ void mma16816(float* acc, const u32* a,
                                         u32 b0, u32 b1) {
    asm volatile(
        "mma.sync.aligned.m16n8k16.row.col.f32.f16.f16.f32 "
        "{%0,%1,%2,%3}, {%4,%5,%6,%7}, {%8,%9}, {%0,%1,%2,%3};"
        : "+f"(acc[0]), "+f"(acc[1]), "+f"(acc[2]), "+f"(acc[3])
        : "r"(a[0]), "r"(a[1]), "r"(a[2]), "r"(a[3]), "r"(b0), "r"(b1));
}
__device__ __forceinline__ u32 smem_u32(const void* p) {
    return (u32)__cvta_generic_to_shared(const_cast<void*>(p));
}
__device__ __forceinline__ float fsel(const float4& v, int t) {
    return (t == 0) ? v.x : (t == 1) ? v.y : (t == 2) ? v.z : v.w;
}

__global__ void __launch_bounds__(THREADS, 2)
tdt_kernel(const float* __restrict__ positions,
           const int*   __restrict__ z,
           const int*   __restrict__ neighbors,
           const float* __restrict__ nmask,
           const float* __restrict__ embedding,
           const float* __restrict__ filtW,
           const float* __restrict__ filtb,
           const float* __restrict__ Wq,
           const float* __restrict__ Wk,
           const float* __restrict__ Wv,
           const float* __restrict__ Wo,
           float*       __restrict__ out)
{
    extern __shared__ __align__(16) float sm[];
    int*    smi = (int*)sm;
    __half* kvh = (__half*)sm;            // kv tile at word 0

    const int tid  = threadIdx.x;
    const int lane = tid & 31;
    const int warp = tid >> 5;            // 0..15
    const int c    = tid & 127;
    const int a4   = tid >> 7;            // 0..3 (atom for per-atom phases)
    const int c4   = tid & 31;
    const int cc   = c4 * 4;

    const int atomBase = blockIdx.x * ATOMS;

    // center embeddings
    sm[SX + a4 * 128 + c] = embedding[z[atomBase + a4] * D_ + c];

    // filtW -> half B tile (stride 136)
    {
        __half* bb = (__half*)sm + SB * 2;
        for (int idx = tid; idx < 32 * 128; idx += THREADS) {
            bb[(idx >> 7) * 136 + (idx & 127)] = __float2half(filtW[idx]);
        }
    }

    // ---- Phase A: per-neighbor scalars (4 atoms x 49 j) ----
    if (tid < 256) {
        const int a = tid >> 6;
        const int j = tid & 63;
        if (j < KP1) {
            const int atom = atomBase + a;
            const int b    = atom >> 9;
            float r, mk; int zjv;
            if (j == 0) { r = 0.01f; mk = 1.0f; zjv = z[atom]; }
            else {
                const int nb = neighbors[atom * K_ + j - 1];
                const float dx = positions[(b * N_ + nb) * 3 + 0] - positions[atom * 3 + 0];
                const float dy = positions[(b * N_ + nb) * 3 + 1] - positions[atom * 3 + 1];
                const float dz = positions[(b * N_ + nb) * 3 + 2] - positions[atom * 3 + 2];
                r   = sqrtf(dx * dx + dy * dy + dz * dz + 1e-12f);
                mk  = nmask[atom * K_ + j - 1];
                zjv = z[b * N_ + nb];
            }
            sm[SLR + a * 64 + j] = __logf(r);
            sm[SC_ + a * 64 + j] = (r < 5.0f) ? (0.5f * (__cosf(r * 0.6283185307f) + 1.0f)) : 0.0f;
            sm[SMK + a * 64 + j] = mk;
            smi[SZJ + a * 64 + j] = zjv;
        }
    }
    __syncthreads();

    // ---- Phase B: gaussians -> fp16 A tile (row = a*64+j, stride 40 halfs) ----
    {
        const float OFF0  = -2.3025850930f;
        const float STEP  =  0.1261942905f;
        const float COEFF = -0.5f / (STEP * STEP);
        __half2* ah = (__half2*)sm;       // half2 index == word index
        for (int idx = tid; idx < ATOMS * KP1 * 16; idx += THREADS) {
            const int a   = idx / 784;
            const int rem = idx - a * 784;
            const int j   = rem >> 4;
            const int gp  = rem & 15;
            const float lr = sm[SLR + a * 64 + j];
            const float o0 = OFF0 + STEP * (float)(2 * gp);
            const float d0 = lr - o0;
            const float d1 = lr - (o0 + STEP);
            ah[SA + (a * 64 + j) * 20 + gp] =
                __floats2half2_rn(__expf(COEFF * d0 * d0), __expf(COEFF * d1 * d1));
        }
        for (int idx = tid; idx < ATOMS * 15 * 16; idx += THREADS) {
            const int a   = idx / 240;
            const int rem = idx - a * 240;
            const int j   = 49 + (rem >> 4);
            const int gp  = rem & 15;
            ah[SA + (a * 64 + j) * 20 + gp] = __floats2half2_rn(0.f, 0.f);
        }
    }
    // ---- C-mult: warp = e-octave (16 x 8 e); 4 atom accumulators ----
    {
        float4 acc[ATOMS];
        #pragma unroll
        for (int a = 0; a < ATOMS; a++) acc[a] = make_float4(0.f, 0.f, 0.f, 0.f);
        #pragma unroll
        for (int i4 = 0; i4 < 2; i4++) {
            float4 xv[ATOMS];
            #pragma unroll
            for (int a = 0; a < ATOMS; a++)
                xv[a] = *(const float4*)&sm[SX + a * 128 + warp * 8 + i4 * 4];
            #pragma unroll
            for (int t = 0; t < 4; t++) {
                const int e = warp * 8 + i4 * 4 + t;
                const float4 wv = *(const float4*)&Wq[e * 128 + cc];
                #pragma unroll
                for (int a = 0; a < ATOMS; a++) {
                    const float xs = fsel(xv[a], t);
                    acc[a].x += xs * wv.x; acc[a].y += xs * wv.y;
                    acc[a].z += xs * wv.z; acc[a].w += xs * wv.w;
                }
            }
        }
        #pragma unroll
        for (int a = 0; a < ATOMS; a++)
            *(float4*)&sm[SKV + warp * 512 + a * 128 + cc] = acc[a];
    }
    __syncthreads();

    // ---- C-reduce -> q ----
    {
        float s = 0.f;
        #pragma unroll
        for (int w = 0; w < 16; w++) s += sm[SKV + w * 512 + a4 * 128 + c];
        sm[SQ + a4 * 128 + c] = s;
    }
    __syncthreads();

    // ---- Phase E: tensor-core filter GEMM + epilogue -> kv (half); 16 warps ----
    {
        const int wA   = warp >> 2;           // atom 0..3
        const int grp  = lane >> 2;
        const int tg   = lane & 3;
        const int jj0  = (warp & 3) * 16 + grp;
        const int jj1  = jj0 + 8;
        const bool ok0 = jj0 < KP1, ok1 = jj1 < KP1;
        const int   zj0 = ok0 ? smi[SZJ + wA * 64 + jj0] : 0;
        const int   zj1 = ok1 ? smi[SZJ + wA * 64 + jj1] : 0;
        const float Cc0 = ok0 ? sm[SC_ + wA * 64 + jj0] : 0.f;
        const float Cc1 = ok1 ? sm[SC_ + wA * 64 + jj1] : 0.f;
        const float* em0 = embedding + zj0 * D_;
        const float* em1 = embedding + zj1 * D_;
        __half* kvb = kvh + wA * KVAH;

        u32 afr[2][4];
        {
            const __half* ab = (const __half*)sm + SA * 2;
            const int lrow = warp * 16 + ((lane & 8) ? 8 : 0) + (lane & 7);
            const int lcol = (lane & 16) ? 8 : 0;
            ldsm4(afr[0], smem_u32(ab + lrow * 40 + lcol));
            ldsm4(afr[1], smem_u32(ab + lrow * 40 + 16 + lcol));
        }
        const __half* bb = (const __half*)sm + SB * 2;
        const int brow = ((lane & 8) ? 8 : 0) + (lane & 7);
        const int bcol = (lane & 16) ? 8 : 0;

        #pragma unroll
        for (int np = 0; np < 8; np++) {
            float acc[8] = {0.f,0.f,0.f,0.f,0.f,0.f,0.f,0.f};
            #pragma unroll
            for (int kk = 0; kk < 2; kk++) {
                u32 bfr[4];
                ldsm4t(bfr, smem_u32(bb + (kk * 16 + brow) * 136 + np * 16 + bcol));
                mma16816(acc + 0, afr[kk], bfr[0], bfr[1]);
                mma16816(acc + 4, afr[kk], bfr[2], bfr[3]);
            }
            #pragma unroll
            for (int t = 0; t < 2; t++) {
                const int c0 = np * 16 + t * 8 + tg * 2;
                const float2 fb2 = *(const float2*)&filtb[c0];
                if (ok0) {
                    const float2 e2 = *(const float2*)&em0[c0];
                    const float v0 = (acc[t*4+0] + fb2.x) * Cc0 * e2.x;
                    const float v1 = (acc[t*4+1] + fb2.y) * Cc0 * e2.y;
                    *(__half2*)&kvb[jj0 * KVH + c0] = __floats2half2_rn(v0, v1);
                }
                if (ok1) {
                    const float2 e2 = *(const float2*)&em1[c0];
                    const float v0 = (acc[t*4+2] + fb2.x) * Cc1 * e2.x;
                    const float v1 = (acc[t*4+3] + fb2.y) * Cc1 * e2.y;
                    *(__half2*)&kvb[jj1 * KVH + c0] = __floats2half2_rn(v0, v1);
                }
            }
        }
    }
    __syncthreads();

    // ---- Phase D: p[a][h][d], warp = 8 d-rows, 4 atoms; fp16 out (aliases dead SB) ----
    {
        __half* ph = (__half*)sm + SPH * 2;
        float4 q[ATOMS];
        #pragma unroll
        for (int a = 0; a < ATOMS; a++)
            q[a] = *(const float4*)&sm[SQ + a * 128 + lane * 4];
        #pragma unroll
        for (int rr = 0; rr < 8; rr++) {
            const int d = warp * 8 + rr;
            const float4 wr = *(const float4*)&Wk[d * D_ + lane * 4];
            #pragma unroll
            for (int a = 0; a < ATOMS; a++) {
                float p = wr.x * q[a].x + wr.y * q[a].y + wr.z * q[a].z + wr.w * q[a].w;
                p += __shfl_xor_sync(0xffffffffu, p, 1);
                p += __shfl_xor_sync(0xffffffffu, p, 2);
                if ((lane & 3) == 0)
                    ph[a * 1088 + (lane >> 2) * 136 + d] = __float2half(p);
            }
        }
    }
    __syncthreads();

    // ---- Phase F: partial scores; warp = (a, rep, dhalf) ----
    {
        const int a     = warp >> 2;
        const int rep   = (warp >> 1) & 1;
        const int dhalf = warp & 1;
        const int j     = rep * 32 + lane;
        float acc[8];
        #pragma unroll
        for (int h = 0; h < 8; h++) acc[h] = 0.f;
        if (j < KP1) {
            const uint4* kvr = (const uint4*)&kvh[a * KVAH + j * KVH + dhalf * 64];
            const __half* pb = (const __half*)sm + SPH * 2 + a * 1088 + dhalf * 64;
            #pragma unroll
            for (int c8 = 0; c8 < 8; c8++) {
                const uint4 raw = kvr[c8];
                const float2 f01 = __half22float2(*(const __half2*)&raw.x);
                const float2 f23 = __half22float2(*(const __half2*)&raw.y);
                const float2 f45 = __half22float2(*(const __half2*)&raw.z);
                const float2 f67 = __half22float2(*(const __half2*)&raw.w);
                #pragma unroll
                for (int h = 0; h < 8; h++) {
                    const uint4 praw = *(const uint4*)&pb[h * 136 + c8 * 8];
                    const float2 p01 = __half22float2(*(const __half2*)&praw.x);
                    const float2 p23 = __half22float2(*(const __half2*)&praw.y);
                    const float2 p45 = __half22float2(*(const __half2*)&praw.z);
                    const float2 p67 = __half22float2(*(const __half2*)&praw.w);
                    acc[h] += f01.x*p01.x + f01.y*p01.y + f23.x*p23.x + f23.y*p23.y
                            + f45.x*p45.x + f45.y*p45.y + f67.x*p67.x + f67.y*p67.y;
                }
            }
        }
        #pragma unroll
        for (int h = 0; h < 8; h++)
            sm[SSC + (warp * 8 + h) * 32 + lane] = acc[h];
    }
    __syncthreads();

    // ---- softmax: warp = (apair, head); writes fp16 attn [a][j][8] ----
    {
        const int h  = warp & 7;
        const int ap = warp >> 3;
        __half* atth = (__half*)sm + SATT * 2;
        #pragma unroll
        for (int aa = 0; aa < 2; aa++) {
            const int a = ap * 2 + aa;
            float v0 = sm[SSC + (((a*2+0)*2+0)*8 + h)*32 + lane]
                     + sm[SSC + (((a*2+0)*2+1)*8 + h)*32 + lane];
            float v1 = (lane < 17) ? sm[SSC + (((a*2+1)*2+0)*8 + h)*32 + lane]
                                   + sm[SSC + (((a*2+1)*2+1)*8 + h)*32 + lane] : 0.f;
            v0 = (sm[SMK + a * 64 + lane] > 0.f) ? v0 * 0.25f : -1e9f;
            const int j1 = lane + 32;
            if (j1 < KP1) v1 = (sm[SMK + a * 64 + j1] > 0.f) ? v1 * 0.25f : -1e9f;
            else          v1 = -3.0e38f;
            float m = fmaxf(v0, v1);
            #pragma unroll
            for (int o = 16; o > 0; o >>= 1)
                m = fmaxf(m, __shfl_xor_sync(0xffffffffu, m, o));
            const float e0 = __expf(v0 - m);
            const float e1 = (j1 < KP1) ? __expf(v1 - m) : 0.f;
            float ssum = e0 + e1;
            #pragma unroll
            for (int o = 16; o > 0; o >>= 1)
                ssum += __shfl_xor_sync(0xffffffffu, ssum, o);
            const float inv = 1.0f / ssum;
            atth[a * 512 + lane * 8 + h] = __float2half(e0 * inv);
            if (j1 < KP1) atth[a * 512 + j1 * 8 + h] = __float2half(e1 * inv);
        }
    }
    __syncthreads();

    // ---- Phase G: u[a][h][c] = sum_j attn[j][h] * kv[j][c]; thread = (a, c) ----
    {
        const __half* kvc  = &kvh[a4 * KVAH + c];
        const __half* atth = (const __half*)sm + SATT * 2 + a4 * 512;
        float acc[8];
        #pragma unroll
        for (int h = 0; h < 8; h++) acc[h] = 0.f;
        #pragma unroll 7
        for (int j = 0; j < KP1; j++) {
            const uint4 praw = *(const uint4*)&atth[j * 8];
            const float2 t01 = __half22float2(*(const __half2*)&praw.x);
            const float2 t23 = __half22float2(*(const __half2*)&praw.y);
            const float2 t45 = __half22float2(*(const __half2*)&praw.z);
            const float2 t67 = __half22float2(*(const __half2*)&praw.w);
            const float kvd = __half2float(kvc[j * KVH]);
            acc[0] += t01.x * kvd; acc[1] += t01.y * kvd;
            acc[2] += t23.x * kvd; acc[3] += t23.y * kvd;
            acc[4] += t45.x * kvd; acc[5] += t45.y * kvd;
            acc[6] += t67.x * kvd; acc[7] += t67.y * kvd;
        }
        #pragma unroll
        for (int h = 0; h < 8; h++) sm[SU + a4 * 1056 + h * 132 + c] = acc[h];
    }
    __syncthreads();

    // ---- H-mult: warp = d-octave (16 x 8 d); 4 atom accumulators ----
    {
        const int h = cc >> 4;
        float4 acc[ATOMS];
        #pragma unroll
        for (int a = 0; a < ATOMS; a++) acc[a] = make_float4(0.f, 0.f, 0.f, 0.f);
        #pragma unroll
        for (int i4 = 0; i4 < 2; i4++) {
            float4 uv[ATOMS];
            #pragma unroll
            for (int a = 0; a < ATOMS; a++)
                uv[a] = *(const float4*)&sm[SU + a * 1056 + h * 132 + warp * 8 + i4 * 4];
            #pragma unroll
            for (int t = 0; t < 4; t++) {
                const int d = warp * 8 + i4 * 4 + t;
                const float4 wv = *(const float4*)&Wv[d * 128 + cc];
                #pragma unroll
                for (int a = 0; a < ATOMS; a++) {
                    const float us = fsel(uv[a], t);
                    acc[a].x += us * wv.x; acc[a].y += us * wv.y;
                    acc[a].z += us * wv.z; acc[a].w += us * wv.w;
                }
            }
        }
        __syncthreads();   // all kv/u consumers done before partials overwrite SKV
        #pragma unroll
        for (int a = 0; a < ATOMS; a++)
            *(float4*)&sm[SKV + warp * 512 + a * 128 + cc] = acc[a];
    }
    __syncthreads();

    // ---- H-reduce -> agg ----
    {
        float s = 0.f;
        #pragma unroll
        for (int w = 0; w < 16; w++) s += sm[SKV + w * 512 + a4 * 128 + c];
        sm[SAGG + a4 * 128 + c] = s;
    }
    __syncthreads();

    // ---- I-mult: out partials (Wo) ----
    {
        float4 acc[ATOMS];
        #pragma unroll
        for (int a = 0; a < ATOMS; a++) acc[a] = make_float4(0.f, 0.f, 0.f, 0.f);
        #pragma unroll
        for (int i4 = 0; i4 < 2; i4++) {
            float4 xv[ATOMS];
            #pragma unroll
            for (int a = 0; a < ATOMS; a++)
                xv[a] = *(const float4*)&sm[SAGG + a * 128 + warp * 8 + i4 * 4];
            #pragma unroll
            for (int t = 0; t < 4; t++) {
                const int e = warp * 8 + i4 * 4 + t;
                const float4 wv = *(const float4*)&Wo[e * 128 + cc];
                #pragma unroll
                for (int a = 0; a < ATOMS; a++) {
                    const float xs = fsel(xv[a], t);
                    acc[a].x += xs * wv.x; acc[a].y += xs * wv.y;
                    acc[a].z += xs * wv.z; acc[a].w += xs * wv.w;
                }
            }
        }
        __syncthreads();   // H-reduce readers done before overwrite
        #pragma unroll
        for (int a = 0; a < ATOMS; a++)
            *(float4*)&sm[SKV + warp * 512 + a * 128 + cc] = acc[a];
    }
    __syncthreads();

    // ---- I-reduce + residual -> out ----
    {
        float s = 0.f;
        #pragma unroll
        for (int w = 0; w < 16; w++) s += sm[SKV + w * 512 + a4 * 128 + c];
        out[(atomBase + a4) * D_ + c] = sm[SX + a4 * 128 + c] + s;
    }
}

} // namespace

extern "C" void kernel_launch(void* const* d_in, const int* in_sizes, int n_in,
                              void* d_out, int out_size) {
    (void)in_sizes; (void)n_in; (void)out_size;
    cudaFuncSetAttribute(tdt_kernel,
                         cudaFuncAttributeMaxDynamicSharedMemorySize, SMEM_BYTES);
    tdt_kernel<<<B_ * N_ / ATOMS, THREADS, SMEM_BYTES>>>(
        (const float*)d_in[0],   // positions
        (const int*)  d_in[1],   // z
        (const int*)  d_in[2],   // neighbors
        (const float*)d_in[3],   // neighbor_mask
        (const float*)d_in[4],   // embedding
        (const float*)d_in[5],   // filt_W
        (const float*)d_in[6],   // filt_b
        (const float*)d_in[7],   // Wq
        (const float*)d_in[8],   // Wk
        (const float*)d_in[9],   // Wv
        (const float*)d_in[10],  // Wo
        (float*)d_out);
}

// round 12
// speedup vs baseline: 1.5804x; 1.1386x over previous
#include <cuda_runtime.h>
#include <cuda_fp16.h>
#include <cstdint>
#include <stdint.h>
#include <math.h>

namespace {

typedef unsigned int u32;
typedef unsigned long long u64;

constexpr int B_  = 16;
constexpr int N_  = 512;
constexpr int K_  = 48;
constexpr int D_  = 128;
constexpr int KP1 = 49;
constexpr int ATOMS = 4;
constexpr int THREADS = 512;

constexpr int KVH  = 136;             // half stride per kv row
constexpr int KVAH = KP1 * KVH;       // 6664 halfs per atom kv tile

// word offsets (liveness audited)
constexpr int SKV   = 0;       // kv half 4*6664 = 13328 w [E..G] ; alias: C/H/I partials 8192 w
constexpr int SA    = 13328;   // gaussian f half tile 256 x 40 halfs = 5120 w [B..E]
constexpr int SSC   = 13328;   // score partials 4096 w (alias, SA dead)      [F..softmax]
constexpr int SU    = 13328;   // u 4*8*132 = 4224 w (alias, SSC dead)        [G..H]
constexpr int SATT  = 18448;   // attn half [a][64][8] = 2048 halfs = 1024 w  [softmax..G]
constexpr int SB    = 19472;   // filtW half 32*136 = 2176 w                  [start..E]
constexpr int SPH   = 19472;   // p half [a][8][136] = 2176 w (alias dead SB) [D..F]
constexpr int SX    = 21648;   // 512
constexpr int SQ    = 22160;   // 512
constexpr int SAGG  = 22672;   // 512
constexpr int SC_   = 23184;   // 256
constexpr int SLR   = 23440;   // 256
constexpr int SMK   = 23696;   // 256
constexpr int SZJ   = 23952;   // 256 ints
constexpr int SMEM_FLOATS = 24208;
constexpr int SMEM_BYTES  = SMEM_FLOATS * 4;   // 96832 -> 2 CTAs/SM

__device__ __forceinline__ void ldsm4(u32* r, u32 a) {
    asm volatile("ldmatrix.sync.aligned.m8n8.x4.shared.b16 {%0,%1,%2,%3}, [%4];"
        : "=r"(r[0]), "=r"(r[1]), "=r"(r[2]), "=r"(r[3]) : "r"(a));
}
__device__ __forceinline__ void ldsm4t(u32* r, u32 a) {
    asm volatile("ldmatrix.sync.aligned.m8n8.x4.trans.shared.b16 {%0,%1,%2,%3}, [%4];"
        : "=r"(r[0]), "=r"(r[1]), "=r"(r[2]), "=r"(r[3]) : "r"(a));
}
__device__ __forceinline__ void mma16816(float* acc, const u32* a,
                                         u32 b0, u32 b1) {
    asm volatile(
        "mma.sync.aligned.m16n8k16.row.col.f32.f16.f16.f32 "
        "{%0,%1,%2,%3}, {%4,%5,%6,%7}, {%8,%9}, {%0,%1,%2,%3};"
        : "+f"(acc[0]), "+f"(acc[1]), "+f"(acc[2]), "+f"(acc[3])
        : "r"(a[0]), "r"(a[1]), "r"(a[2]), "r"(a[3]), "r"(b0), "r"(b1));
}
__device__ __forceinline__ u32 smem_u32(const void* p) {
    return (u32)__cvta_generic_to_shared(const_cast<void*>(p));
}
__device__ __forceinline__ float fsel(const float4& v, int t) {
    return (t == 0) ? v.x : (t == 1) ? v.y : (t == 2) ? v.z : v.w;
}
// packed fp32x2 helpers (Blackwell FFMA2 path; ptxas won't auto-fuse)
__device__ __forceinline__ u64 pack2(float x) {
    u64 r; asm("mov.b64 %0, {%1, %1};" : "=l"(r) : "f"(x)); return r;
}
__device__ __forceinline__ void ffma2(u64& acc, u64 a, u64 b) {
    asm("fma.rn.f32x2 %0, %1, %2, %0;" : "+l"(acc) : "l"(a), "l"(b));
}
__device__ __forceinline__ void unpack2(u64 v, float& lo, float& hi) {
    asm("mov.b64 {%0, %1}, %2;" : "=f"(lo), "=f"(hi) : "l"(v));
}

__global__ void __launch_bounds__(THREADS, 2)
tdt_kernel(const float* __restrict__ positions,
           const int*   __restrict__ z,
           const int*   __restrict__ neighbors,
           const float* __restrict__ nmask,
           const float* __restrict__ embedding,
           const float* __restrict__ filtW,
           const float* __restrict__ filtb,
           const float* __restrict__ Wq,
           const float* __restrict__ Wk,
           const float* __restrict__ Wv,
           const float* __restrict__ Wo,
           float*       __restrict__ out)
{
    extern __shared__ __align__(16) float sm[];
    int*    smi = (int*)sm;
    __half* kvh = (__half*)sm;            // kv tile at word 0

    const int tid  = threadIdx.x;
    const int lane = tid & 31;
    const int warp = tid >> 5;            // 0..15
    const int c    = tid & 127;
    const int a4   = tid >> 7;            // 0..3
    const int c4   = tid & 31;
    const int cc   = c4 * 4;

    const int atomBase = blockIdx.x * ATOMS;

    // center embeddings
    sm[SX + a4 * 128 + c] = embedding[z[atomBase + a4] * D_ + c];

    // filtW -> half B tile (stride 136)
    {
        __half* bb = (__half*)sm + SB * 2;
        for (int idx = tid; idx < 32 * 128; idx += THREADS) {
            bb[(idx >> 7) * 136 + (idx & 127)] = __float2half(filtW[idx]);
        }
    }

    // ---- Phase A: per-neighbor scalars (4 atoms x 49 j) ----
    if (tid < 256) {
        const int a = tid >> 6;
        const int j = tid & 63;
        if (j < KP1) {
            const int atom = atomBase + a;
            const int b    = atom >> 9;
            float r, mk; int zjv;
            if (j == 0) { r = 0.01f; mk = 1.0f; zjv = z[atom]; }
            else {
                const int nb = neighbors[atom * K_ + j - 1];
                const float dx = positions[(b * N_ + nb) * 3 + 0] - positions[atom * 3 + 0];
                const float dy = positions[(b * N_ + nb) * 3 + 1] - positions[atom * 3 + 1];
                const float dz = positions[(b * N_ + nb) * 3 + 2] - positions[atom * 3 + 2];
                r   = sqrtf(dx * dx + dy * dy + dz * dz + 1e-12f);
                mk  = nmask[atom * K_ + j - 1];
                zjv = z[b * N_ + nb];
            }
            sm[SLR + a * 64 + j] = __logf(r);
            sm[SC_ + a * 64 + j] = (r < 5.0f) ? (0.5f * (__cosf(r * 0.6283185307f) + 1.0f)) : 0.0f;
            sm[SMK + a * 64 + j] = mk;
            smi[SZJ + a * 64 + j] = zjv;
        }
    }
    __syncthreads();

    // ---- Phase B: gaussians -> fp16 A tile (row = a*64+j, stride 40 halfs) ----
    {
        const float OFF0  = -2.3025850930f;
        const float STEP  =  0.1261942905f;
        const float COEFF = -0.5f / (STEP * STEP);
        __half2* ah = (__half2*)sm;       // half2 index == word index
        for (int idx = tid; idx < ATOMS * KP1 * 16; idx += THREADS) {
            const int a   = idx / 784;
            const int rem = idx - a * 784;
            const int j   = rem >> 4;
            const int gp  = rem & 15;
            const float lr = sm[SLR + a * 64 + j];
            const float o0 = OFF0 + STEP * (float)(2 * gp);
            const float d0 = lr - o0;
            const float d1 = lr - (o0 + STEP);
            ah[SA + (a * 64 + j) * 20 + gp] =
                __floats2half2_rn(__expf(COEFF * d0 * d0), __expf(COEFF * d1 * d1));
        }
        for (int idx = tid; idx < ATOMS * 15 * 16; idx += THREADS) {
            const int a   = idx / 240;
            const int rem = idx - a * 240;
            const int j   = 49 + (rem >> 4);
            const int gp  = rem & 15;
            ah[SA + (a * 64 + j) * 20 + gp] = __floats2half2_rn(0.f, 0.f);
        }
    }
    // ---- C-mult: warp = e-octave; FFMA2 packed ----
    {
        u64 a01[ATOMS], a23[ATOMS];
        #pragma unroll
        for (int a = 0; a < ATOMS; a++) { a01[a] = 0ull; a23[a] = 0ull; }
        #pragma unroll
        for (int i4 = 0; i4 < 2; i4++) {
            float4 xv[ATOMS];
            #pragma unroll
            for (int a = 0; a < ATOMS; a++)
                xv[a] = *(const float4*)&sm[SX + a * 128 + warp * 8 + i4 * 4];
            #pragma unroll
            for (int t = 0; t < 4; t++) {
                const int e = warp * 8 + i4 * 4 + t;
                const ulonglong2 wv = *(const ulonglong2*)&Wq[e * 128 + cc];
                #pragma unroll
                for (int a = 0; a < ATOMS; a++) {
                    const u64 xs2 = pack2(fsel(xv[a], t));
                    ffma2(a01[a], xs2, wv.x);
                    ffma2(a23[a], xs2, wv.y);
                }
            }
        }
        #pragma unroll
        for (int a = 0; a < ATOMS; a++) {
            float4 r;
            unpack2(a01[a], r.x, r.y); unpack2(a23[a], r.z, r.w);
            *(float4*)&sm[SKV + warp * 512 + a * 128 + cc] = r;
        }
    }
    __syncthreads();

    // ---- C-reduce -> q ----
    {
        float s = 0.f;
        #pragma unroll
        for (int w = 0; w < 16; w++) s += sm[SKV + w * 512 + a4 * 128 + c];
        sm[SQ + a4 * 128 + c] = s;
    }
    __syncthreads();

    // ---- Phase E: tensor-core filter GEMM + epilogue -> kv (half); 16 warps ----
    {
        const int wA   = warp >> 2;
        const int grp  = lane >> 2;
        const int tg   = lane & 3;
        const int jj0  = (warp & 3) * 16 + grp;
        const int jj1  = jj0 + 8;
        const bool ok0 = jj0 < KP1, ok1 = jj1 < KP1;
        const int   zj0 = ok0 ? smi[SZJ + wA * 64 + jj0] : 0;
        const int   zj1 = ok1 ? smi[SZJ + wA * 64 + jj1] : 0;
        const float Cc0 = ok0 ? sm[SC_ + wA * 64 + jj0] : 0.f;
        const float Cc1 = ok1 ? sm[SC_ + wA * 64 + jj1] : 0.f;
        const float* em0 = embedding + zj0 * D_;
        const float* em1 = embedding + zj1 * D_;
        __half* kvb = kvh + wA * KVAH;

        u32 afr[2][4];
        {
            const __half* ab = (const __half*)sm + SA * 2;
            const int lrow = warp * 16 + ((lane & 8) ? 8 : 0) + (lane & 7);
            const int lcol = (lane & 16) ? 8 : 0;
            ldsm4(afr[0], smem_u32(ab + lrow * 40 + lcol));
            ldsm4(afr[1], smem_u32(ab + lrow * 40 + 16 + lcol));
        }
        const __half* bb = (const __half*)sm + SB * 2;
        const int brow = ((lane & 8) ? 8 : 0) + (lane & 7);
        const int bcol = (lane & 16) ? 8 : 0;

        #pragma unroll
        for (int np = 0; np < 8; np++) {
            float acc[8] = {0.f,0.f,0.f,0.f,0.f,0.f,0.f,0.f};
            #pragma unroll
            for (int kk = 0; kk < 2; kk++) {
                u32 bfr[4];
                ldsm4t(bfr, smem_u32(bb + (kk * 16 + brow) * 136 + np * 16 + bcol));
                mma16816(acc + 0, afr[kk], bfr[0], bfr[1]);
                mma16816(acc + 4, afr[kk], bfr[2], bfr[3]);
            }
            #pragma unroll
            for (int t = 0; t < 2; t++) {
                const int c0 = np * 16 + t * 8 + tg * 2;
                const float2 fb2 = *(const float2*)&filtb[c0];
                if (ok0) {
                    const float2 e2 = *(const float2*)&em0[c0];
                    const float v0 = (acc[t*4+0] + fb2.x) * Cc0 * e2.x;
                    const float v1 = (acc[t*4+1] + fb2.y) * Cc0 * e2.y;
                    *(__half2*)&kvb[jj0 * KVH + c0] = __floats2half2_rn(v0, v1);
                }
                if (ok1) {
                    const float2 e2 = *(const float2*)&em1[c0];
                    const float v0 = (acc[t*4+2] + fb2.x) * Cc1 * e2.x;
                    const float v1 = (acc[t*4+3] + fb2.y) * Cc1 * e2.y;
                    *(__half2*)&kvb[jj1 * KVH + c0] = __floats2half2_rn(v0, v1);
                }
            }
        }
    }
    __syncthreads();

    // ---- Phase D: p[a][h][d], warp = 8 d-rows, 4 atoms; fp16 out ----
    {
        __half* ph = (__half*)sm + SPH * 2;
        float4 q[ATOMS];
        #pragma unroll
        for (int a = 0; a < ATOMS; a++)
            q[a] = *(const float4*)&sm[SQ + a * 128 + lane * 4];
        #pragma unroll
        for (int rr = 0; rr < 8; rr++) {
            const int d = warp * 8 + rr;
            const float4 wr = *(const float4*)&Wk[d * D_ + lane * 4];
            #pragma unroll
            for (int a = 0; a < ATOMS; a++) {
                float p = wr.x * q[a].x + wr.y * q[a].y + wr.z * q[a].z + wr.w * q[a].w;
                p += __shfl_xor_sync(0xffffffffu, p, 1);
                p += __shfl_xor_sync(0xffffffffu, p, 2);
                if ((lane & 3) == 0)
                    ph[a * 1088 + (lane >> 2) * 136 + d] = __float2half(p);
            }
        }
    }
    __syncthreads();

    // ---- Phase F: partial scores in HALF2 (no converts); warp = (a, rep, dhalf) ----
    {
        const int a     = warp >> 2;
        const int rep   = (warp >> 1) & 1;
        const int dhalf = warp & 1;
        const int j     = rep * 32 + lane;
        __half2 acc2[8];
        #pragma unroll
        for (int h = 0; h < 8; h++) acc2[h] = __floats2half2_rn(0.f, 0.f);
        if (j < KP1) {
            const uint4* kvr = (const uint4*)&kvh[a * KVAH + j * KVH + dhalf * 64];
            const __half* pb = (const __half*)sm + SPH * 2 + a * 1088 + dhalf * 64;
            #pragma unroll
            for (int c8 = 0; c8 < 8; c8++) {
                const uint4 kraw = kvr[c8];
                const __half2 k01 = *(const __half2*)&kraw.x;
                const __half2 k23 = *(const __half2*)&kraw.y;
                const __half2 k45 = *(const __half2*)&kraw.z;
                const __half2 k67 = *(const __half2*)&kraw.w;
                #pragma unroll
                for (int h = 0; h < 8; h++) {
                    const uint4 praw = *(const uint4*)&pb[h * 136 + c8 * 8];
                    __half2 t = __hmul2(k01, *(const __half2*)&praw.x);
                    t = __hfma2(k23, *(const __half2*)&praw.y, t);
                    t = __hfma2(k45, *(const __half2*)&praw.z, t);
                    t = __hfma2(k67, *(const __half2*)&praw.w, t);
                    acc2[h] = __hadd2(acc2[h], t);
                }
            }
        }
        #pragma unroll
        for (int h = 0; h < 8; h++)
            sm[SSC + (warp * 8 + h) * 32 + lane] =
                __low2float(acc2[h]) + __high2float(acc2[h]);
    }
    __syncthreads();

    // ---- softmax: warp = (apair, head); writes fp16 attn [a][j][8] ----
    {
        const int h  = warp & 7;
        const int ap = warp >> 3;
        __half* atth = (__half*)sm + SATT * 2;
        #pragma unroll
        for (int aa = 0; aa < 2; aa++) {
            const int a = ap * 2 + aa;
            float v0 = sm[SSC + (((a*2+0)*2+0)*8 + h)*32 + lane]
                     + sm[SSC + (((a*2+0)*2+1)*8 + h)*32 + lane];
            float v1 = (lane < 17) ? sm[SSC + (((a*2+1)*2+0)*8 + h)*32 + lane]
                                   + sm[SSC + (((a*2+1)*2+1)*8 + h)*32 + lane] : 0.f;
            v0 = (sm[SMK + a * 64 + lane] > 0.f) ? v0 * 0.25f : -1e9f;
            const int j1 = lane + 32;
            if (j1 < KP1) v1 = (sm[SMK + a * 64 + j1] > 0.f) ? v1 * 0.25f : -1e9f;
            else          v1 = -3.0e38f;
            float m = fmaxf(v0, v1);
            #pragma unroll
            for (int o = 16; o > 0; o >>= 1)
                m = fmaxf(m, __shfl_xor_sync(0xffffffffu, m, o));
            const float e0 = __expf(v0 - m);
            const float e1 = (j1 < KP1) ? __expf(v1 - m) : 0.f;
            float ssum = e0 + e1;
            #pragma unroll
            for (int o = 16; o > 0; o >>= 1)
                ssum += __shfl_xor_sync(0xffffffffu, ssum, o);
            const float inv = 1.0f / ssum;
            atth[a * 512 + lane * 8 + h] = __float2half(e0 * inv);
            if (j1 < KP1) atth[a * 512 + j1 * 8 + h] = __float2half(e1 * inv);
        }
    }
    __syncthreads();

    // ---- Phase G: u in HALF2; thread = (a, c) ----
    {
        const __half* kvc  = &kvh[a4 * KVAH + c];
        const __half* atth = (const __half*)sm + SATT * 2 + a4 * 512;
        __half2 acc2[4];
        #pragma unroll
        for (int i = 0; i < 4; i++) acc2[i] = __floats2half2_rn(0.f, 0.f);
        #pragma unroll 7
        for (int j = 0; j < KP1; j++) {
            const uint4 praw = *(const uint4*)&atth[j * 8];
            const __half2 kv2 = __half2half2(kvc[j * KVH]);
            acc2[0] = __hfma2(*(const __half2*)&praw.x, kv2, acc2[0]);
            acc2[1] = __hfma2(*(const __half2*)&praw.y, kv2, acc2[1]);
            acc2[2] = __hfma2(*(const __half2*)&praw.z, kv2, acc2[2]);
            acc2[3] = __hfma2(*(const __half2*)&praw.w, kv2, acc2[3]);
        }
        #pragma unroll
        for (int i = 0; i < 4; i++) {
            sm[SU + a4 * 1056 + (2*i+0) * 132 + c] = __low2float(acc2[i]);
            sm[SU + a4 * 1056 + (2*i+1) * 132 + c] = __high2float(acc2[i]);
        }
    }
    __syncthreads();

    // ---- H-mult: warp = d-octave; FFMA2 packed ----
    {
        const int h = cc >> 4;
        u64 a01[ATOMS], a23[ATOMS];
        #pragma unroll
        for (int a = 0; a < ATOMS; a++) { a01[a] = 0ull; a23[a] = 0ull; }
        #pragma unroll
        for (int i4 = 0; i4 < 2; i4++) {
            float4 uv[ATOMS];
            #pragma unroll
            for (int a = 0; a < ATOMS; a++)
                uv[a] = *(const float4*)&sm[SU + a * 1056 + h * 132 + warp * 8 + i4 * 4];
            #pragma unroll
            for (int t = 0; t < 4; t++) {
                const int d = warp * 8 + i4 * 4 + t;
                const ulonglong2 wv = *(const ulonglong2*)&Wv[d * 128 + cc];
                #pragma unroll
                for (int a = 0; a < ATOMS; a++) {
                    const u64 us2 = pack2(fsel(uv[a], t));
                    ffma2(a01[a], us2, wv.x);
                    ffma2(a23[a], us2, wv.y);
                }
            }
        }
        __syncthreads();   // kv/u consumers done before partials overwrite SKV
        #pragma unroll
        for (int a = 0; a < ATOMS; a++) {
            float4 r;
            unpack2(a01[a], r.x, r.y); unpack2(a23[a], r.z, r.w);
            *(float4*)&sm[SKV + warp * 512 + a * 128 + cc] = r;
        }
    }
    __syncthreads();

    // ---- H-reduce -> agg ----
    {
        float s = 0.f;
        #pragma unroll
        for (int w = 0; w < 16; w++) s += sm[SKV + w * 512 + a4 * 128 + c];
        sm[SAGG + a4 * 128 + c] = s;
    }
    __syncthreads();

    // ---- I-mult: out partials (Wo); FFMA2 packed ----
    {
        u64 a01[ATOMS], a23[ATOMS];
        #pragma unroll
        for (int a = 0; a < ATOMS; a++) { a01[a] = 0ull; a23[a] = 0ull; }
        #pragma unroll
        for (int i4 = 0; i4 < 2; i4++) {
            float4 xv[ATOMS];
            #pragma unroll
            for (int a = 0; a < ATOMS; a++)
                xv[a] = *(const float4*)&sm[SAGG + a * 128 + warp * 8 + i4 * 4];
            #pragma unroll
            for (int t = 0; t < 4; t++) {
                const int e = warp * 8 + i4 * 4 + t;
                const ulonglong2 wv = *(const ulonglong2*)&Wo[e * 128 + cc];
                #pragma unroll
                for (int a = 0; a < ATOMS; a++) {
                    const u64 xs2 = pack2(fsel(xv[a], t));
                    ffma2(a01[a], xs2, wv.x);
                    ffma2(a23[a], xs2, wv.y);
                }
            }
        }
        __syncthreads();   // H-reduce readers done before overwrite
        #pragma unroll
        for (int a = 0; a < ATOMS; a++) {
            float4 r;
            unpack2(a01[a], r.x, r.y); unpack2(a23[a], r.z, r.w);
            *(float4*)&sm[SKV + warp * 512 + a * 128 + cc] = r;
        }
    }
    __syncthreads();

    // ---- I-reduce + residual -> out ----
    {
        float s = 0.f;
        #pragma unroll
        for (int w = 0; w < 16; w++) s += sm[SKV + w * 512 + a4 * 128 + c];
        out[(atomBase + a4) * D_ + c] = sm[SX + a4 * 128 + c] + s;
    }
}

} // namespace

extern "C" void kernel_launch(void* const* d_in, const int* in_sizes, int n_in,
                              void* d_out, int out_size) {
    (void)in_sizes; (void)n_in; (void)out_size;
    cudaFuncSetAttribute(tdt_kernel,
                         cudaFuncAttributeMaxDynamicSharedMemorySize, SMEM_BYTES);
    tdt_kernel<<<B_ * N_ / ATOMS, THREADS, SMEM_BYTES>>>(
        (const float*)d_in[0],   // positions
        (const int*)  d_in[1],   // z
        (const int*)  d_in[2],   // neighbors
        (const float*)d_in[3],   // neighbor_mask
        (const float*)d_in[4],   // embedding
        (const float*)d_in[5],   // filt_W
        (const float*)d_in[6],   // filt_b
        (const float*)d_in[7],   // Wq
        (const float*)d_in[8],   // Wk
        (const float*)d_in[9],   // Wv
        (const float*)d_in[10],  // Wo
        (float*)d_out);
}

// round 13
// speedup vs baseline: 1.5994x; 1.0120x over previous
#include <cuda_runtime.h>
#include <cuda_fp16.h>
#include <cstdint>
#include <stdint.h>
#include <math.h>

namespace {

typedef unsigned int u32;
typedef unsigned long long u64;

constexpr int B_  = 16;
constexpr int N_  = 512;
constexpr int K_  = 48;
constexpr int D_  = 128;
constexpr int KP1 = 49;
constexpr int ATOMS = 4;
constexpr int THREADS = 512;

constexpr int KVH  = 136;             // half stride per kv row
constexpr int KVAH = KP1 * KVH;       // 6664 halfs per atom kv tile

// word offsets (liveness audited)
constexpr int SKV   = 0;       // kv half 4*6664 = 13328 w [E..G] ; alias: C/H/I partials 4096 w
constexpr int SA    = 13328;   // gaussian f half tile 256 x 40 halfs = 5120 w [B..E]
constexpr int SSC   = 13328;   // score partials 4096 w (alias, SA dead)      [F..softmax]
constexpr int SU    = 13328;   // u 4*8*132 = 4224 w (alias, SSC dead)        [G..H]
constexpr int SATT  = 18448;   // attn half [a][64][8] = 2048 halfs = 1024 w  [softmax..G]
constexpr int SB    = 19472;   // filtW half 32*136 = 2176 w                  [start..E]
constexpr int SPH   = 19472;   // p half [a][8][136] = 2176 w (alias dead SB) [D..F]
constexpr int SX    = 21648;   // 512
constexpr int SQ    = 22160;   // 512
constexpr int SAGG  = 22672;   // 512
constexpr int SC_   = 23184;   // 256
constexpr int SLR   = 23440;   // 256
constexpr int SMK   = 23696;   // 256
constexpr int SZJ   = 23952;   // 256 ints
constexpr int SMEM_FLOATS = 24208;
constexpr int SMEM_BYTES  = SMEM_FLOATS * 4;   // 96832 -> 2 CTAs/SM

__device__ __forceinline__ void ldsm4(u32* r, u32 a) {
    asm volatile("ldmatrix.sync.aligned.m8n8.x4.shared.b16 {%0,%1,%2,%3}, [%4];"
        : "=r"(r[0]), "=r"(r[1]), "=r"(r[2]), "=r"(r[3]) : "r"(a));
}
__device__ __forceinline__ void ldsm4t(u32* r, u32 a) {
    asm volatile("ldmatrix.sync.aligned.m8n8.x4.trans.shared.b16 {%0,%1,%2,%3}, [%4];"
        : "=r"(r[0]), "=r"(r[1]), "=r"(r[2]), "=r"(r[3]) : "r"(a));
}
__device__ __forceinline__ void mma16816(float* acc, const u32* a,
                                         u32 b0, u32 b1) {
    asm volatile(
        "mma.sync.aligned.m16n8k16.row.col.f32.f16.f16.f32 "
        "{%0,%1,%2,%3}, {%4,%5,%6,%7}, {%8,%9}, {%0,%1,%2,%3};"
        : "+f"(acc[0]), "+f"(acc[1]), "+f"(acc[2]), "+f"(acc[3])
        : "r"(a[0]), "r"(a[1]), "r"(a[2]), "r"(a[3]), "r"(b0), "r"(b1));
}
__device__ __forceinline__ u32 smem_u32(const void* p) {
    return (u32)__cvta_generic_to_shared(const_cast<void*>(p));
}
__device__ __forceinline__ float fsel(const float4& v, int t) {
    return (t == 0) ? v.x : (t == 1) ? v.y : (t == 2) ? v.z : v.w;
}
// packed fp32x2 helpers (Blackwell FFMA2 path)
__device__ __forceinline__ u64 pack2(float x) {
    u64 r; asm("mov.b64 %0, {%1, %1};" : "=l"(r) : "f"(x)); return r;
}
__device__ __forceinline__ void ffma2(u64& acc, u64 a, u64 b) {
    asm("fma.rn.f32x2 %0, %1, %2, %0;" : "+l"(acc) : "l"(a), "l"(b));
}
__device__ __forceinline__ void unpack2(u64 v, float& lo, float& hi) {
    asm("mov.b64 {%0, %1}, %2;" : "=f"(lo), "=f"(hi) : "l"(v));
}

__global__ void __launch_bounds__(THREADS, 2)
tdt_kernel(const float* __restrict__ positions,
           const int*   __restrict__ z,
           const int*   __restrict__ neighbors,
           const float* __restrict__ nmask,
           const float* __restrict__ embedding,
           const float* __restrict__ filtW,
           const float* __restrict__ filtb,
           const float* __restrict__ Wq,
           const float* __restrict__ Wk,
           const float* __restrict__ Wv,
           const float* __restrict__ Wo,
           float*       __restrict__ out)
{
    extern __shared__ __align__(16) float sm[];
    int*    smi = (int*)sm;
    __half* kvh = (__half*)sm;            // kv tile at word 0

    const int tid  = threadIdx.x;
    const int lane = tid & 31;
    const int warp = tid >> 5;            // 0..15
    const int c    = tid & 127;
    const int a4   = tid >> 7;            // 0..3
    // GEMV decomposition: 8 e-groups x 2 c-halves, lane owns 2 columns
    const int eg   = warp >> 1;           // 0..7
    const int ch   = warp & 1;            // 0..1
    const int ccc  = ch * 64 + lane * 2;  // column pair base (even)

    const int atomBase = blockIdx.x * ATOMS;

    // center embeddings
    sm[SX + a4 * 128 + c] = embedding[z[atomBase + a4] * D_ + c];

    // filtW -> half B tile (stride 136)
    {
        __half* bb = (__half*)sm + SB * 2;
        for (int idx = tid; idx < 32 * 128; idx += THREADS) {
            bb[(idx >> 7) * 136 + (idx & 127)] = __float2half(filtW[idx]);
        }
    }

    // ---- Phase A: per-neighbor scalars (4 atoms x 49 j) ----
    if (tid < 256) {
        const int a = tid >> 6;
        const int j = tid & 63;
        if (j < KP1) {
            const int atom = atomBase + a;
            const int b    = atom >> 9;
            float r, mk; int zjv;
            if (j == 0) { r = 0.01f; mk = 1.0f; zjv = z[atom]; }
            else {
                const int nb = neighbors[atom * K_ + j - 1];
                const float dx = positions[(b * N_ + nb) * 3 + 0] - positions[atom * 3 + 0];
                const float dy = positions[(b * N_ + nb) * 3 + 1] - positions[atom * 3 + 1];
                const float dz = positions[(b * N_ + nb) * 3 + 2] - positions[atom * 3 + 2];
                r   = sqrtf(dx * dx + dy * dy + dz * dz + 1e-12f);
                mk  = nmask[atom * K_ + j - 1];
                zjv = z[b * N_ + nb];
            }
            sm[SLR + a * 64 + j] = __logf(r);
            sm[SC_ + a * 64 + j] = (r < 5.0f) ? (0.5f * (__cosf(r * 0.6283185307f) + 1.0f)) : 0.0f;
            sm[SMK + a * 64 + j] = mk;
            smi[SZJ + a * 64 + j] = zjv;
        }
    }
    __syncthreads();

    // ---- Phase B: gaussians -> fp16 A tile (row = a*64+j, stride 40 halfs) ----
    {
        const float OFF0  = -2.3025850930f;
        const float STEP  =  0.1261942905f;
        const float COEFF = -0.5f / (STEP * STEP);
        __half2* ah = (__half2*)sm;       // half2 index == word index
        for (int idx = tid; idx < ATOMS * KP1 * 16; idx += THREADS) {
            const int a   = idx / 784;
            const int rem = idx - a * 784;
            const int j   = rem >> 4;
            const int gp  = rem & 15;
            const float lr = sm[SLR + a * 64 + j];
            const float o0 = OFF0 + STEP * (float)(2 * gp);
            const float d0 = lr - o0;
            const float d1 = lr - (o0 + STEP);
            ah[SA + (a * 64 + j) * 20 + gp] =
                __floats2half2_rn(__expf(COEFF * d0 * d0), __expf(COEFF * d1 * d1));
        }
        for (int idx = tid; idx < ATOMS * 15 * 16; idx += THREADS) {
            const int a   = idx / 240;
            const int rem = idx - a * 240;
            const int j   = 49 + (rem >> 4);
            const int gp  = rem & 15;
            ah[SA + (a * 64 + j) * 20 + gp] = __floats2half2_rn(0.f, 0.f);
        }
    }
    // ---- C-mult: warp = (e-group of 16, c-half); FFMA2 packed ----
    {
        u64 acc[ATOMS];
        #pragma unroll
        for (int a = 0; a < ATOMS; a++) acc[a] = 0ull;
        #pragma unroll
        for (int i4 = 0; i4 < 4; i4++) {
            float4 xv[ATOMS];
            #pragma unroll
            for (int a = 0; a < ATOMS; a++)
                xv[a] = *(const float4*)&sm[SX + a * 128 + eg * 16 + i4 * 4];
            #pragma unroll
            for (int t = 0; t < 4; t++) {
                const int e = eg * 16 + i4 * 4 + t;
                const u64 wv = *(const u64*)&Wq[e * 128 + ccc];
                #pragma unroll
                for (int a = 0; a < ATOMS; a++)
                    ffma2(acc[a], pack2(fsel(xv[a], t)), wv);
            }
        }
        #pragma unroll
        for (int a = 0; a < ATOMS; a++) {
            float2 r; unpack2(acc[a], r.x, r.y);
            *(float2*)&sm[SKV + eg * 512 + a * 128 + ccc] = r;
        }
    }
    __syncthreads();

    // ---- C-reduce -> q (8 partials) ----
    {
        float s = 0.f;
        #pragma unroll
        for (int w = 0; w < 8; w++) s += sm[SKV + w * 512 + a4 * 128 + c];
        sm[SQ + a4 * 128 + c] = s;
    }
    __syncthreads();

    // ---- Phase E: tensor-core filter GEMM + epilogue -> kv (half); 16 warps ----
    {
        const int wA   = warp >> 2;
        const int grp  = lane >> 2;
        const int tg   = lane & 3;
        const int jj0  = (warp & 3) * 16 + grp;
        const int jj1  = jj0 + 8;
        const bool ok0 = jj0 < KP1, ok1 = jj1 < KP1;
        const int   zj0 = ok0 ? smi[SZJ + wA * 64 + jj0] : 0;
        const int   zj1 = ok1 ? smi[SZJ + wA * 64 + jj1] : 0;
        const float Cc0 = ok0 ? sm[SC_ + wA * 64 + jj0] : 0.f;
        const float Cc1 = ok1 ? sm[SC_ + wA * 64 + jj1] : 0.f;
        const float* em0 = embedding + zj0 * D_;
        const float* em1 = embedding + zj1 * D_;
        __half* kvb = kvh + wA * KVAH;

        u32 afr[2][4];
        {
            const __half* ab = (const __half*)sm + SA * 2;
            const int lrow = warp * 16 + ((lane & 8) ? 8 : 0) + (lane & 7);
            const int lcol = (lane & 16) ? 8 : 0;
            ldsm4(afr[0], smem_u32(ab + lrow * 40 + lcol));
            ldsm4(afr[1], smem_u32(ab + lrow * 40 + 16 + lcol));
        }
        const __half* bb = (const __half*)sm + SB * 2;
        const int brow = ((lane & 8) ? 8 : 0) + (lane & 7);
        const int bcol = (lane & 16) ? 8 : 0;

        #pragma unroll
        for (int np = 0; np < 8; np++) {
            float acc[8] = {0.f,0.f,0.f,0.f,0.f,0.f,0.f,0.f};
            #pragma unroll
            for (int kk = 0; kk < 2; kk++) {
                u32 bfr[4];
                ldsm4t(bfr, smem_u32(bb + (kk * 16 + brow) * 136 + np * 16 + bcol));
                mma16816(acc + 0, afr[kk], bfr[0], bfr[1]);
                mma16816(acc + 4, afr[kk], bfr[2], bfr[3]);
            }
            #pragma unroll
            for (int t = 0; t < 2; t++) {
                const int c0 = np * 16 + t * 8 + tg * 2;
                const float2 fb2 = *(const float2*)&filtb[c0];
                if (ok0) {
                    const float2 e2 = *(const float2*)&em0[c0];
                    const float v0 = (acc[t*4+0] + fb2.x) * Cc0 * e2.x;
                    const float v1 = (acc[t*4+1] + fb2.y) * Cc0 * e2.y;
                    *(__half2*)&kvb[jj0 * KVH + c0] = __floats2half2_rn(v0, v1);
                }
                if (ok1) {
                    const float2 e2 = *(const float2*)&em1[c0];
                    const float v0 = (acc[t*4+2] + fb2.x) * Cc1 * e2.x;
                    const float v1 = (acc[t*4+3] + fb2.y) * Cc1 * e2.y;
                    *(__half2*)&kvb[jj1 * KVH + c0] = __floats2half2_rn(v0, v1);
                }
            }
        }
    }
    __syncthreads();

    // ---- Phase D: p[a][h][d], warp = 8 d-rows, 4 atoms; fp16 out ----
    {
        __half* ph = (__half*)sm + SPH * 2;
        float4 q[ATOMS];
        #pragma unroll
        for (int a = 0; a < ATOMS; a++)
            q[a] = *(const float4*)&sm[SQ + a * 128 + lane * 4];
        #pragma unroll
        for (int rr = 0; rr < 8; rr++) {
            const int d = warp * 8 + rr;
            const float4 wr = *(const float4*)&Wk[d * D_ + lane * 4];
            #pragma unroll
            for (int a = 0; a < ATOMS; a++) {
                float p = wr.x * q[a].x + wr.y * q[a].y + wr.z * q[a].z + wr.w * q[a].w;
                p += __shfl_xor_sync(0xffffffffu, p, 1);
                p += __shfl_xor_sync(0xffffffffu, p, 2);
                if ((lane & 3) == 0)
                    ph[a * 1088 + (lane >> 2) * 136 + d] = __float2half(p);
            }
        }
    }
    __syncthreads();

    // ---- Phase F: partial scores in HALF2; warp = (a, rep, dhalf) ----
    {
        const int a     = warp >> 2;
        const int rep   = (warp >> 1) & 1;
        const int dhalf = warp & 1;
        const int j     = rep * 32 + lane;
        __half2 acc2[8];
        #pragma unroll
        for (int h = 0; h < 8; h++) acc2[h] = __floats2half2_rn(0.f, 0.f);
        if (j < KP1) {
            const uint4* kvr = (const uint4*)&kvh[a * KVAH + j * KVH + dhalf * 64];
            const __half* pb = (const __half*)sm + SPH * 2 + a * 1088 + dhalf * 64;
            #pragma unroll
            for (int c8 = 0; c8 < 8; c8++) {
                const uint4 kraw = kvr[c8];
                const __half2 k01 = *(const __half2*)&kraw.x;
                const __half2 k23 = *(const __half2*)&kraw.y;
                const __half2 k45 = *(const __half2*)&kraw.z;
                const __half2 k67 = *(const __half2*)&kraw.w;
                #pragma unroll
                for (int h = 0; h < 8; h++) {
                    const uint4 praw = *(const uint4*)&pb[h * 136 + c8 * 8];
                    __half2 t = __hmul2(k01, *(const __half2*)&praw.x);
                    t = __hfma2(k23, *(const __half2*)&praw.y, t);
                    t = __hfma2(k45, *(const __half2*)&praw.z, t);
                    t = __hfma2(k67, *(const __half2*)&praw.w, t);
                    acc2[h] = __hadd2(acc2[h], t);
                }
            }
        }
        #pragma unroll
        for (int h = 0; h < 8; h++)
            sm[SSC + (warp * 8 + h) * 32 + lane] =
                __low2float(acc2[h]) + __high2float(acc2[h]);
    }
    __syncthreads();

    // ---- softmax: warp = (apair, head); writes fp16 attn [a][j][8] ----
    {
        const int h  = warp & 7;
        const int ap = warp >> 3;
        __half* atth = (__half*)sm + SATT * 2;
        #pragma unroll
        for (int aa = 0; aa < 2; aa++) {
            const int a = ap * 2 + aa;
            float v0 = sm[SSC + (((a*2+0)*2+0)*8 + h)*32 + lane]
                     + sm[SSC + (((a*2+0)*2+1)*8 + h)*32 + lane];
            float v1 = (lane < 17) ? sm[SSC + (((a*2+1)*2+0)*8 + h)*32 + lane]
                                   + sm[SSC + (((a*2+1)*2+1)*8 + h)*32 + lane] : 0.f;
            v0 = (sm[SMK + a * 64 + lane] > 0.f) ? v0 * 0.25f : -1e9f;
            const int j1 = lane + 32;
            if (j1 < KP1) v1 = (sm[SMK + a * 64 + j1] > 0.f) ? v1 * 0.25f : -1e9f;
            else          v1 = -3.0e38f;
            float m = fmaxf(v0, v1);
            #pragma unroll
            for (int o = 16; o > 0; o >>= 1)
                m = fmaxf(m, __shfl_xor_sync(0xffffffffu, m, o));
            const float e0 = __expf(v0 - m);
            const float e1 = (j1 < KP1) ? __expf(v1 - m) : 0.f;
            float ssum = e0 + e1;
            #pragma unroll
            for (int o = 16; o > 0; o >>= 1)
                ssum += __shfl_xor_sync(0xffffffffu, ssum, o);
            const float inv = 1.0f / ssum;
            atth[a * 512 + lane * 8 + h] = __float2half(e0 * inv);
            if (j1 < KP1) atth[a * 512 + j1 * 8 + h] = __float2half(e1 * inv);
        }
    }
    __syncthreads();

    // ---- Phase G: u in HALF2; thread = (a, c) ----
    {
        const __half* kvc  = &kvh[a4 * KVAH + c];
        const __half* atth = (const __half*)sm + SATT * 2 + a4 * 512;
        __half2 acc2[4];
        #pragma unroll
        for (int i = 0; i < 4; i++) acc2[i] = __floats2half2_rn(0.f, 0.f);
        #pragma unroll 7
        for (int j = 0; j < KP1; j++) {
            const uint4 praw = *(const uint4*)&atth[j * 8];
            const __half2 kv2 = __half2half2(kvc[j * KVH]);
            acc2[0] = __hfma2(*(const __half2*)&praw.x, kv2, acc2[0]);
            acc2[1] = __hfma2(*(const __half2*)&praw.y, kv2, acc2[1]);
            acc2[2] = __hfma2(*(const __half2*)&praw.z, kv2, acc2[2]);
            acc2[3] = __hfma2(*(const __half2*)&praw.w, kv2, acc2[3]);
        }
        #pragma unroll
        for (int i = 0; i < 4; i++) {
            sm[SU + a4 * 1056 + (2*i+0) * 132 + c] = __low2float(acc2[i]);
            sm[SU + a4 * 1056 + (2*i+1) * 132 + c] = __high2float(acc2[i]);
        }
    }
    __syncthreads();

    // ---- H-mult: warp = (d-group of 16, c-half); FFMA2 packed ----
    {
        const int h = ccc >> 4;           // both lane columns share head
        u64 acc[ATOMS];
        #pragma unroll
        for (int a = 0; a < ATOMS; a++) acc[a] = 0ull;
        #pragma unroll
        for (int i4 = 0; i4 < 4; i4++) {
            float4 uv[ATOMS];
            #pragma unroll
            for (int a = 0; a < ATOMS; a++)
                uv[a] = *(const float4*)&sm[SU + a * 1056 + h * 132 + eg * 16 + i4 * 4];
            #pragma unroll
            for (int t = 0; t < 4; t++) {
                const int d = eg * 16 + i4 * 4 + t;
                const u64 wv = *(const u64*)&Wv[d * 128 + ccc];
                #pragma unroll
                for (int a = 0; a < ATOMS; a++)
                    ffma2(acc[a], pack2(fsel(uv[a], t)), wv);
            }
        }
        __syncthreads();   // kv/u consumers done before partials overwrite SKV
        #pragma unroll
        for (int a = 0; a < ATOMS; a++) {
            float2 r; unpack2(acc[a], r.x, r.y);
            *(float2*)&sm[SKV + eg * 512 + a * 128 + ccc] = r;
        }
    }
    __syncthreads();

    // ---- H-reduce -> agg (8 partials) ----
    {
        float s = 0.f;
        #pragma unroll
        for (int w = 0; w < 8; w++) s += sm[SKV + w * 512 + a4 * 128 + c];
        sm[SAGG + a4 * 128 + c] = s;
    }
    __syncthreads();

    // ---- I-mult: warp = (e-group of 16, c-half); FFMA2 packed ----
    {
        u64 acc[ATOMS];
        #pragma unroll
        for (int a = 0; a < ATOMS; a++) acc[a] = 0ull;
        #pragma unroll
        for (int i4 = 0; i4 < 4; i4++) {
            float4 xv[ATOMS];
            #pragma unroll
            for (int a = 0; a < ATOMS; a++)
                xv[a] = *(const float4*)&sm[SAGG + a * 128 + eg * 16 + i4 * 4];
            #pragma unroll
            for (int t = 0; t < 4; t++) {
                const int e = eg * 16 + i4 * 4 + t;
                const u64 wv = *(const u64*)&Wo[e * 128 + ccc];
                #pragma unroll
                for (int a = 0; a < ATOMS; a++)
                    ffma2(acc[a], pack2(fsel(xv[a], t)), wv);
            }
        }
        __syncthreads();   // H-reduce readers done before overwrite
        #pragma unroll
        for (int a = 0; a < ATOMS; a++) {
            float2 r; unpack2(acc[a], r.x, r.y);
            *(float2*)&sm[SKV + eg * 512 + a * 128 + ccc] = r;
        }
    }
    __syncthreads();

    // ---- I-reduce + residual -> out ----
    {
        float s = 0.f;
        #pragma unroll
        for (int w = 0; w < 8; w++) s += sm[SKV + w * 512 + a4 * 128 + c];
        out[(atomBase + a4) * D_ + c] = sm[SX + a4 * 128 + c] + s;
    }
}

} // namespace

extern "C" void kernel_launch(void* const* d_in, const int* in_sizes, int n_in,
                              void* d_out, int out_size) {
    (void)in_sizes; (void)n_in; (void)out_size;
    cudaFuncSetAttribute(tdt_kernel,
                         cudaFuncAttributeMaxDynamicSharedMemorySize, SMEM_BYTES);
    tdt_kernel<<<B_ * N_ / ATOMS, THREADS, SMEM_BYTES>>>(
        (const float*)d_in[0],   // positions
        (const int*)  d_in[1],   // z
        (const int*)  d_in[2],   // neighbors
        (const float*)d_in[3],   // neighbor_mask
        (const float*)d_in[4],   // embedding
        (const float*)d_in[5],   // filt_W
        (const float*)d_in[6],   // filt_b
        (const float*)d_in[7],   // Wq
        (const float*)d_in[8],   // Wk
        (const float*)d_in[9],   // Wv
        (const float*)d_in[10],  // Wo
        (float*)d_out);
}